// round 5
// baseline (speedup 1.0000x reference)
#include <cuda_runtime.h>
typedef unsigned long long u64;
#define NA_ 40000
#define NE_ 150000

#define W_WB 0
#define W_WQKV 4096
#define W_WO 16384
#define W_W1 20480
#define W_W2 24576
#define B_BB 28672
#define B_BQKV (B_BB+64)
#define B_BO (B_BB+256)
#define B_G1 (B_BB+320)
#define B_BE1 (B_BB+384)
#define B_BF1 (B_BB+448)
#define B_BF2 (B_BB+512)
#define B_G2 (B_BB+576)
#define B_BE2 (B_BB+640)
#define SCR 29376
// per-edge scratch: xC[64][8]=512 | KC[*]=512 | VC=512 | QC=256
#define XCo 0
#define KCo 512
#define VCo 1024
#define QCo 1536
#define EF 1792
#define WF (2*EF)
#define NGRP 8
#define SMEM_BYTES ((SCR+NGRP*WF)*4)   // 232192 <= 232448

__device__ __align__(16) float g_accum[2][NA_][256];
__device__ __align__(16) float g_cnt[2][NA_];

__global__ void zero_kernel() {
    float4* a = (float4*)&g_accum[0][0][0];
    const int n4 = 2*NA_*64;
    for (int i = blockIdx.x*blockDim.x+threadIdx.x; i < n4; i += gridDim.x*blockDim.x)
        a[i] = make_float4(0.f,0.f,0.f,0.f);
    float4* c = (float4*)&g_cnt[0][0];
    for (int i = blockIdx.x*blockDim.x+threadIdx.x; i < 2*NA_/4; i += gridDim.x*blockDim.x)
        c[i] = make_float4(0.f,0.f,0.f,0.f);
}

__device__ __forceinline__ u64 pk2(float a, float b) {
    u64 r; asm("mov.b64 %0,{%1,%2};" : "=l"(r) : "f"(a), "f"(b)); return r;
}
__device__ __forceinline__ void upk2(u64 v, float& a, float& b) {
    asm("mov.b64 {%0,%1},%2;" : "=f"(a), "=f"(b) : "l"(v));
}
__device__ __forceinline__ void fma2(u64& d, u64 a, u64 b) {
    asm("fma.rn.f32x2 %0,%1,%2,%0;" : "+l"(d) : "l"(a), "l"(b));
}
__device__ __forceinline__ void lnpair(float& v0, float& v1, float ga, float gb,
                                       float ba, float bb2) {
    float sum = v0+v1, sq = v0*v0+v1*v1;
#pragma unroll
    for (int o = 16; o; o >>= 1) {
        sum += __shfl_xor_sync(~0u, sum, o);
        sq  += __shfl_xor_sync(~0u, sq, o);
    }
    float m = sum*(1.f/64.f);
    float rs = rsqrtf(sq*(1.f/64.f)-m*m+1e-5f);
    v0 = (v0-m)*rs*ga+ba; v1 = (v1-m)*rs*gb+bb2;
}
__device__ __forceinline__ void red2(float* p, float a, float b) {
    asm volatile("red.global.add.v2.f32 [%0],{%1,%2};" :: "l"(p), "f"(a), "f"(b) : "memory");
}

__global__ void __launch_bounds__(512,1) edge_kernel(
    const float* __restrict__ xA, const float* __restrict__ xB,
    const int* __restrict__ e_ba, const int* __restrict__ e_aa,
    const float* __restrict__ Wb, const float* __restrict__ bb,
    const float* __restrict__ Wqkv, const float* __restrict__ bqkv,
    const float* __restrict__ Wo, const float* __restrict__ bo,
    const float* __restrict__ g1, const float* __restrict__ be1,
    const float* __restrict__ W1, const float* __restrict__ bf1,
    const float* __restrict__ W2, const float* __restrict__ bf2,
    const float* __restrict__ g2, const float* __restrict__ be2)
{
    extern __shared__ float sm[];
    const int k = blockIdx.y, tid = threadIdx.x;
    {
        const float* s1 = Wb + k*4096;  const float* s2 = Wo + k*4096;
        const float* s3 = W1 + k*4096;  const float* s4 = W2 + k*4096;
        for (int i = tid; i < 4096; i += 512) {
            int o = i>>6, c = i&63;
            sm[W_WB + c*64 + o] = s1[i];
            sm[W_WO + c*64 + o] = s2[i];
            sm[W_W1 + c*64 + o] = s3[i];
            sm[W_W2 + c*64 + o] = s4[i];
        }
        const float* sq = Wqkv + k*12288;
        for (int i = tid; i < 12288; i += 512) {
            int o = i>>6, c = i&63;
            sm[W_WQKV + c*192 + o] = sq[i];
        }
        if (tid < 64) {
            sm[B_BB+tid]=bb[k*64+tid];   sm[B_BO+tid]=bo[k*64+tid];
            sm[B_G1+tid]=g1[k*64+tid];   sm[B_BE1+tid]=be1[k*64+tid];
            sm[B_BF1+tid]=bf1[k*64+tid]; sm[B_BF2+tid]=bf2[k*64+tid];
            sm[B_G2+tid]=g2[k*64+tid];   sm[B_BE2+tid]=be2[k*64+tid];
        }
        if (tid < 192) sm[B_BQKV+tid] = bqkv[k*192+tid];
    }
    __syncthreads();

    const float* xdst = xA;
    const float* xsrc = (k==0) ? xB : xA;
    const int* Es = (k==0) ? e_ba : e_aa;
    const int* Ed = Es + NE_;
    float* accum = &g_accum[k][0][0];
    float* cnt = &g_cnt[k][0];

    const int lane = tid & 31, wrp = tid >> 5;
    const int grp = wrp >> 1, w = wrp & 1;       // 2 warps per edge-pair group
    const int ch0 = 2*lane;
    const int barid = 1 + grp;
    float* scr = sm + SCR + grp*WF;
    const float* WbT = sm+W_WB;  const float* WqT = sm+W_WQKV;
    const float* WoT = sm+W_WO;  const float* W1T = sm+W_W1;
    const float* W2T = sm+W_W2;
    const int tw = 2*w;          // this warp's token offset (output tokens tw, tw+1)
    const int kw = 4*w;          // this warp's kv token offset (tokens kw..kw+3)

#define GBAR() asm volatile("bar.sync %0, 64;" :: "r"(barid) : "memory")

    for (int p = blockIdx.x*NGRP + grp; p < NE_/2; p += 148*NGRP) {
        const int e0 = 2*p, e1 = 2*p+1;
        const int di0 = Ed[e0], di1 = Ed[e1];
        float xln[2][2][2];   // [edge][chhalf][token]

        // ---- staging: warp w stages edge w ----
        {
            const int sii = w ? Es[e1] : Es[e0];
            const int dii = w ? di1 : di0;
            const float* xd = xdst + (size_t)dii*256;
            const float* xp = xsrc + (size_t)sii*256;
            float* xc = scr + w*EF + XCo;
            float* vc = scr + w*EF + VCo;
            float2 dv[4], sv[4];
#pragma unroll
            for (int s = 0; s < 4; s++) {
                dv[s] = *(const float2*)(xd + s*64 + ch0);
                sv[s] = *(const float2*)(xp + s*64 + ch0);
            }
            *(float4*)(xc + ch0*8)     = make_float4(dv[0].x,dv[1].x,dv[2].x,dv[3].x);
            *(float4*)(xc + ch0*8 + 8) = make_float4(dv[0].y,dv[1].y,dv[2].y,dv[3].y);
            *(float4*)(vc + ch0*4)     = make_float4(sv[0].x,sv[1].x,sv[2].x,sv[3].x);
            *(float4*)(vc + ch0*4 + 4) = make_float4(sv[0].y,sv[1].y,sv[2].y,sv[3].y);
        }
        GBAR();

        // ---- b_proj: output tokens (4+tw, 5+tw), both edges ----
        {
            float b0f,b1f; upk2(*(const u64*)(sm+B_BB+ch0), b0f,b1f);
            u64 acc[2][2];
            acc[0][0]=acc[1][0]=pk2(b0f,b0f);
            acc[0][1]=acc[1][1]=pk2(b1f,b1f);
            const float* v0p = scr+VCo; const float* v1p = scr+EF+VCo;
#pragma unroll 4
            for (int c = 0; c < 64; c++) {
                float w0,w1; upk2(*(const u64*)(WbT+c*64+ch0), w0,w1);
                u64 w00=pk2(w0,w0), w11=pk2(w1,w1);
                u64 x0 = *(const u64*)(v0p + c*4 + tw);
                u64 x1 = *(const u64*)(v1p + c*4 + tw);
                fma2(acc[0][0],x0,w00); fma2(acc[0][1],x0,w11);
                fma2(acc[1][0],x1,w00); fma2(acc[1][1],x1,w11);
            }
#pragma unroll
            for (int ee=0; ee<2; ee++) {
                float* xc = scr + ee*EF + XCo;
                *(u64*)(xc + ch0*8 + 4 + tw)     = acc[ee][0];
                *(u64*)(xc + (ch0+1)*8 + 4 + tw) = acc[ee][1];
            }
        }
        GBAR();

        // ---- QKV: q tokens (tw,tw+1); k,v tokens (kw..kw+3), both edges ----
        {
            float bqa,bqb,bka,bkb,bva,bvb;
            upk2(*(const u64*)(sm+B_BQKV+ch0), bqa,bqb);
            upk2(*(const u64*)(sm+B_BQKV+64+ch0), bka,bkb);
            upk2(*(const u64*)(sm+B_BQKV+128+ch0), bva,bvb);
            u64 aq[2][2], ak[2][2][2], av[2][2][2];
#pragma unroll
            for (int ee=0; ee<2; ee++) {
                aq[ee][0]=pk2(bqa,bqa); aq[ee][1]=pk2(bqb,bqb);
#pragma unroll
                for (int q=0;q<2;q++) {
                    ak[ee][0][q]=pk2(bka,bka); ak[ee][1][q]=pk2(bkb,bkb);
                    av[ee][0][q]=pk2(bva,bva); av[ee][1][q]=pk2(bvb,bvb);
                }
            }
#pragma unroll 2
            for (int c = 0; c < 64; c++) {
                const float* wr = WqT + c*192 + ch0;
                float q0,q1,k0,k1,v0,v1;
                upk2(*(const u64*)(wr), q0,q1);
                upk2(*(const u64*)(wr+64), k0,k1);
                upk2(*(const u64*)(wr+128), v0,v1);
                u64 wq0=pk2(q0,q0),wq1=pk2(q1,q1),wk0=pk2(k0,k0),
                    wk1=pk2(k1,k1),wv0=pk2(v0,v0),wv1=pk2(v1,v1);
#pragma unroll
                for (int ee=0; ee<2; ee++) {
                    const float* xc = scr + ee*EF + XCo + c*8;
                    u64 xq = *(const u64*)(xc + tw);
                    ulonglong2 xkv = *(const ulonglong2*)(xc + kw);
                    fma2(aq[ee][0],xq,wq0); fma2(aq[ee][1],xq,wq1);
                    fma2(ak[ee][0][0],xkv.x,wk0); fma2(ak[ee][0][1],xkv.y,wk0);
                    fma2(ak[ee][1][0],xkv.x,wk1); fma2(ak[ee][1][1],xkv.y,wk1);
                    fma2(av[ee][0][0],xkv.x,wv0); fma2(av[ee][0][1],xkv.y,wv0);
                    fma2(av[ee][1][0],xkv.x,wv1); fma2(av[ee][1][1],xkv.y,wv1);
                }
            }
#pragma unroll
            for (int ee=0; ee<2; ee++) {
                float* qc = scr + ee*EF + QCo;
                float* kc = scr + ee*EF + KCo;
                float* vc = scr + ee*EF + VCo;
#pragma unroll
                for (int j=0; j<2; j++) {
                    int ch = ch0 + j;
                    float a,b;
                    upk2(aq[ee][j],a,b);
                    qc[tw*64+ch]=a; qc[(tw+1)*64+ch]=b;
#pragma unroll
                    for (int q=0;q<2;q++) {
                        int t0 = kw + 2*q;
                        upk2(ak[ee][j][q],a,b); kc[t0*64+ch]=a; kc[(t0+1)*64+ch]=b;
                        upk2(av[ee][j][q],a,b); vc[t0*64+ch]=a; vc[(t0+1)*64+ch]=b;
                    }
                }
            }
        }
        GBAR();

        // ---- attention: 16 tasks/warp: (ee, h, s in {tw,tw+1}) ----
        float ov[16]; float inv = 0.f;
        const int aee = lane>>3, ah = (lane>>1)&3, as = tw + (lane&1);
        if (lane < 16) {
            const float* base = scr + aee*EF;
            const float* qr = base + QCo + as*64 + ah*16;
            float qv[16];
            *(float4*)(qv)    = *(const float4*)(qr);
            *(float4*)(qv+4)  = *(const float4*)(qr+4);
            *(float4*)(qv+8)  = *(const float4*)(qr+8);
            *(float4*)(qv+12) = *(const float4*)(qr+12);
            float sc[8], mx = -1e30f;
#pragma unroll
            for (int t = 0; t < 8; t++) {
                const float* kr = base + KCo + t*64 + ah*16;
                float kv[16];
                *(float4*)(kv)    = *(const float4*)(kr);
                *(float4*)(kv+4)  = *(const float4*)(kr+4);
                *(float4*)(kv+8)  = *(const float4*)(kr+8);
                *(float4*)(kv+12) = *(const float4*)(kr+12);
                float d = 0.f;
#pragma unroll
                for (int dd = 0; dd < 16; dd++) d += qv[dd]*kv[dd];
                d *= 0.25f;
                sc[t] = d; mx = fmaxf(mx, d);
            }
            float sum = 0.f;
#pragma unroll
            for (int t = 0; t < 8; t++) { sc[t] = __expf(sc[t]-mx); sum += sc[t]; }
            inv = 1.0f/sum;
#pragma unroll
            for (int dd = 0; dd < 16; dd++) ov[dd] = 0.f;
#pragma unroll
            for (int t = 0; t < 8; t++) {
                const float* vr = base + VCo + t*64 + ah*16;
                float vv[16];
                *(float4*)(vv)    = *(const float4*)(vr);
                *(float4*)(vv+4)  = *(const float4*)(vr+4);
                *(float4*)(vv+8)  = *(const float4*)(vr+8);
                *(float4*)(vv+12) = *(const float4*)(vr+12);
                float pw = sc[t];
#pragma unroll
                for (int dd = 0; dd < 16; dd++) ov[dd] += pw*vv[dd];
            }
        }
        GBAR();   // all q/k/v reads complete before O overlays QC
        if (lane < 16) {
            float* od = scr + aee*EF + QCo;
#pragma unroll
            for (int dd = 0; dd < 16; dd++) od[(ah*16+dd)*4 + as] = ov[dd]*inv;
        }
        __syncwarp();

        // ---- Wo + residual + LN1 (tokens tw,tw+1) ----
        {
            float b0f,b1f; upk2(*(const u64*)(sm+B_BO+ch0), b0f,b1f);
            u64 acc[2][2];
            acc[0][0]=acc[1][0]=pk2(b0f,b0f);
            acc[0][1]=acc[1][1]=pk2(b1f,b1f);
            u64 rx[2][2];
#pragma unroll
            for (int ee=0; ee<2; ee++) {
                const float* xc = scr + ee*EF + XCo;
                rx[ee][0] = *(const u64*)(xc + ch0*8 + tw);
                rx[ee][1] = *(const u64*)(xc + (ch0+1)*8 + tw);
            }
            const float* o0p = scr+QCo; const float* o1p = scr+EF+QCo;
#pragma unroll 4
            for (int c = 0; c < 64; c++) {
                float w0,w1; upk2(*(const u64*)(WoT+c*64+ch0), w0,w1);
                u64 w00=pk2(w0,w0), w11=pk2(w1,w1);
                u64 x0 = *(const u64*)(o0p + c*4 + tw);
                u64 x1 = *(const u64*)(o1p + c*4 + tw);
                fma2(acc[0][0],x0,w00); fma2(acc[0][1],x0,w11);
                fma2(acc[1][0],x1,w00); fma2(acc[1][1],x1,w11);
            }
            float ga,gb,ba,bb2;
            upk2(*(const u64*)(sm+B_G1+ch0), ga,gb);
            upk2(*(const u64*)(sm+B_BE1+ch0), ba,bb2);
#pragma unroll
            for (int ee=0; ee<2; ee++) {
                float a0[2],a1[2],r0[2],r1[2];
                upk2(acc[ee][0],a0[0],a0[1]); upk2(acc[ee][1],a1[0],a1[1]);
                upk2(rx[ee][0],r0[0],r0[1]); upk2(rx[ee][1],r1[0],r1[1]);
#pragma unroll
                for (int t = 0; t < 2; t++) {
                    float v0 = a0[t]+r0[t], v1 = a1[t]+r1[t];
                    lnpair(v0, v1, ga, gb, ba, bb2);
                    xln[ee][0][t]=v0; xln[ee][1][t]=v1;
                }
                float* xc = scr + ee*EF + XCo;
                *(u64*)(xc + ch0*8 + tw)     = pk2(xln[ee][0][0],xln[ee][0][1]);
                *(u64*)(xc + (ch0+1)*8 + tw) = pk2(xln[ee][1][0],xln[ee][1][1]);
            }
        }
        __syncwarp();

        // ---- FF1: relu -> KC[ch][4] (tokens tw,tw+1) ----
        {
            float b0f,b1f; upk2(*(const u64*)(sm+B_BF1+ch0), b0f,b1f);
            u64 acc[2][2];
            acc[0][0]=acc[1][0]=pk2(b0f,b0f);
            acc[0][1]=acc[1][1]=pk2(b1f,b1f);
            const float* x0p = scr+XCo; const float* x1p = scr+EF+XCo;
#pragma unroll 4
            for (int c = 0; c < 64; c++) {
                float w0,w1; upk2(*(const u64*)(W1T+c*64+ch0), w0,w1);
                u64 w00=pk2(w0,w0), w11=pk2(w1,w1);
                u64 x0 = *(const u64*)(x0p + c*8 + tw);
                u64 x1 = *(const u64*)(x1p + c*8 + tw);
                fma2(acc[0][0],x0,w00); fma2(acc[0][1],x0,w11);
                fma2(acc[1][0],x1,w00); fma2(acc[1][1],x1,w11);
            }
#pragma unroll
            for (int ee=0; ee<2; ee++) {
                float* kc = scr + ee*EF + KCo;
                float a,b;
                upk2(acc[ee][0],a,b);
                *(u64*)(kc + ch0*4 + tw)     = pk2(fmaxf(a,0.f),fmaxf(b,0.f));
                upk2(acc[ee][1],a,b);
                *(u64*)(kc + (ch0+1)*4 + tw) = pk2(fmaxf(a,0.f),fmaxf(b,0.f));
            }
        }
        __syncwarp();

        // ---- FF2 + residual + LN2 + scatter (tokens tw,tw+1) ----
        {
            float b0f,b1f; upk2(*(const u64*)(sm+B_BF2+ch0), b0f,b1f);
            u64 acc[2][2];
            acc[0][0]=acc[1][0]=pk2(b0f,b0f);
            acc[0][1]=acc[1][1]=pk2(b1f,b1f);
            const float* h0p = scr+KCo; const float* h1p = scr+EF+KCo;
#pragma unroll 4
            for (int f = 0; f < 64; f++) {
                float w0,w1; upk2(*(const u64*)(W2T+f*64+ch0), w0,w1);
                u64 w00=pk2(w0,w0), w11=pk2(w1,w1);
                u64 x0 = *(const u64*)(h0p + f*4 + tw);
                u64 x1 = *(const u64*)(h1p + f*4 + tw);
                fma2(acc[0][0],x0,w00); fma2(acc[0][1],x0,w11);
                fma2(acc[1][0],x1,w00); fma2(acc[1][1],x1,w11);
            }
            float ga,gb,ba,bb2;
            upk2(*(const u64*)(sm+B_G2+ch0), ga,gb);
            upk2(*(const u64*)(sm+B_BE2+ch0), ba,bb2);
#pragma unroll
            for (int ee=0; ee<2; ee++) {
                float a0[2],a1[2];
                upk2(acc[ee][0],a0[0],a0[1]); upk2(acc[ee][1],a1[0],a1[1]);
                float* outp = accum + (size_t)(ee?di1:di0)*256;
#pragma unroll
                for (int t = 0; t < 2; t++) {
                    float v0 = a0[t] + xln[ee][0][t];
                    float v1 = a1[t] + xln[ee][1][t];
                    lnpair(v0, v1, ga, gb, ba, bb2);
                    red2(outp + (tw+t)*64 + ch0, v0, v1);
                }
            }
            if (w == 0 && lane == 0) { atomicAdd(cnt+di0, 1.0f); atomicAdd(cnt+di1, 1.0f); }
        }
        GBAR();   // protect xC/VC/KC before next iteration's staging
    }
#undef GBAR
}

__global__ void __launch_bounds__(256) final_kernel(
    const float* __restrict__ Wout, const float* __restrict__ bout,
    float* __restrict__ out)
{
    __shared__ float WoT[2048];
    __shared__ float xs[8][64];
    const int tid = threadIdx.x;
    for (int i = tid; i < 2048; i += 256) {
        int o = i>>6, c = i&63;
        WoT[c*32+o] = Wout[i];
    }
    __syncthreads();
    const int wrp = tid>>5, lane = tid&31;
    const int n = blockIdx.x*8 + wrp;
    if (n >= NA_) return;
    float c0 = g_cnt[0][n], c1 = g_cnt[1][n];
    float i0 = (c0>0.f) ? 0.5f/c0 : 0.f;
    float i1 = (c1>0.f) ? 0.5f/c1 : 0.f;
    const float* a0p = &g_accum[0][n][0];
    const float* a1p = &g_accum[1][n][0];
    float s0 = 0.f, s1 = 0.f;
#pragma unroll
    for (int t = 0; t < 4; t++) {
        s0 += a0p[t*64+lane]*i0 + a1p[t*64+lane]*i1;
        s1 += a0p[t*64+32+lane]*i0 + a1p[t*64+32+lane]*i1;
    }
    xs[wrp][lane] = s0; xs[wrp][lane+32] = s1;
    __syncwarp();
    float lg = 4.0f*bout[lane];
#pragma unroll
    for (int c = 0; c < 64; c++) lg += xs[wrp][c]*WoT[c*32+lane];
    float m = lg;
#pragma unroll
    for (int o = 16; o; o >>= 1) m = fmaxf(m, __shfl_xor_sync(~0u, m, o));
    float ev = __expf(lg - m);
    float sum = ev;
#pragma unroll
    for (int o = 16; o; o >>= 1) sum += __shfl_xor_sync(~0u, sum, o);
    out[(size_t)n*32 + lane] = ev/sum;
}

extern "C" void kernel_launch(void* const* d_in, const int* in_sizes, int n_in,
                              void* d_out, int out_size) {
    const float* xA   = (const float*)d_in[0];
    const float* xB   = (const float*)d_in[1];
    const int*   e_ba = (const int*)d_in[2];
    const int*   e_aa = (const int*)d_in[3];
    const float* Wb   = (const float*)d_in[4];
    const float* bb   = (const float*)d_in[5];
    const float* Wqkv = (const float*)d_in[6];
    const float* bqkv = (const float*)d_in[7];
    const float* Wo   = (const float*)d_in[8];
    const float* bo   = (const float*)d_in[9];
    const float* g1   = (const float*)d_in[10];
    const float* be1  = (const float*)d_in[11];
    const float* W1   = (const float*)d_in[12];
    const float* bf1  = (const float*)d_in[13];
    const float* W2   = (const float*)d_in[14];
    const float* bf2  = (const float*)d_in[15];
    const float* g2   = (const float*)d_in[16];
    const float* be2  = (const float*)d_in[17];
    const float* Wout = (const float*)d_in[18];
    const float* bout = (const float*)d_in[19];

    cudaFuncSetAttribute(edge_kernel,
                         cudaFuncAttributeMaxDynamicSharedMemorySize, SMEM_BYTES);
    // Order: edge first (g_accum is zero-initialized at module load; zero_kernel
    // at the END primes the accumulators for the next call — identical work
    // every call, graph-capturable, deterministic).
    edge_kernel<<<dim3(148,2), 512, SMEM_BYTES>>>(
        xA, xB, e_ba, e_aa, Wb, bb, Wqkv, bqkv, Wo, bo,
        g1, be1, W1, bf1, W2, bf2, g2, be2);
    final_kernel<<<(NA_+7)/8, 256>>>(Wout, bout, (float*)d_out);
    zero_kernel<<<1024, 256>>>();
}

// round 8
// speedup vs baseline: 1.2726x; 1.2726x over previous
#include <cuda_runtime.h>
typedef unsigned long long u64;
#define NA_ 40000
#define NE_ 150000

#define W_WB 0
#define W_WQKV 4096
#define W_WO 16384
#define W_W1 20480
#define W_W2 24576
#define B_BB 28672
#define B_BQKV (B_BB+64)
#define B_BO (B_BB+256)
#define B_G1 (B_BB+320)
#define B_BE1 (B_BB+384)
#define B_BF1 (B_BB+448)
#define B_BF2 (B_BB+512)
#define B_G2 (B_BB+576)
#define B_BE2 (B_BB+640)
#define SCR 29376
// per-edge region (1024 floats):
//  [0:512)    A: xC[64][8]  -> K[8][64] -> o[64][4](0:256)+x'[64][4](256:512)
//  [512:768)  B: src[64][4] -> FF hidden[64][4]
//  [768:1024) Q: q[4][64]
#define EF2 1024
#define PF 2048
#define NW 12
#define SMEM_BYTES ((SCR+NW*PF)*4)   // 215808 B

__device__ __align__(16) float g_accum[2][NA_][256];
__device__ __align__(16) float g_cnt[2][NA_];

__global__ void zero_kernel() {
    float4* a = (float4*)&g_accum[0][0][0];
    const int n4 = 2*NA_*64;
    for (int i = blockIdx.x*blockDim.x+threadIdx.x; i < n4; i += gridDim.x*blockDim.x)
        a[i] = make_float4(0.f,0.f,0.f,0.f);
    float4* c = (float4*)&g_cnt[0][0];
    for (int i = blockIdx.x*blockDim.x+threadIdx.x; i < 2*NA_/4; i += gridDim.x*blockDim.x)
        c[i] = make_float4(0.f,0.f,0.f,0.f);
}

__device__ __forceinline__ u64 pk2(float a, float b) {
    u64 r; asm("mov.b64 %0,{%1,%2};" : "=l"(r) : "f"(a), "f"(b)); return r;
}
__device__ __forceinline__ void upk2(u64 v, float& a, float& b) {
    asm("mov.b64 {%0,%1},%2;" : "=f"(a), "=f"(b) : "l"(v));
}
__device__ __forceinline__ void fma2(u64& d, u64 a, u64 b) {
    asm("fma.rn.f32x2 %0,%1,%2,%0;" : "+l"(d) : "l"(a), "l"(b));
}
__device__ __forceinline__ void lnpair(float& v0, float& v1, float ga, float gb,
                                       float ba, float bb2) {
    float sum = v0+v1, sq = v0*v0+v1*v1;
#pragma unroll
    for (int o = 16; o; o >>= 1) {
        sum += __shfl_xor_sync(~0u, sum, o);
        sq  += __shfl_xor_sync(~0u, sq, o);
    }
    float m = sum*(1.f/64.f);
    float rs = rsqrtf(sq*(1.f/64.f)-m*m+1e-5f);
    v0 = (v0-m)*rs*ga+ba; v1 = (v1-m)*rs*gb+bb2;
}
__device__ __forceinline__ void red2(float* p, float a, float b) {
    asm volatile("red.global.add.v2.f32 [%0],{%1,%2};" :: "l"(p), "f"(a), "f"(b) : "memory");
}

__global__ void __launch_bounds__(384,1) edge_kernel(
    const float* __restrict__ xA, const float* __restrict__ xB,
    const int* __restrict__ e_ba, const int* __restrict__ e_aa,
    const float* __restrict__ Wb, const float* __restrict__ bb,
    const float* __restrict__ Wqkv, const float* __restrict__ bqkv,
    const float* __restrict__ Wo, const float* __restrict__ bo,
    const float* __restrict__ g1, const float* __restrict__ be1,
    const float* __restrict__ W1, const float* __restrict__ bf1,
    const float* __restrict__ W2, const float* __restrict__ bf2,
    const float* __restrict__ g2, const float* __restrict__ be2)
{
    extern __shared__ float sm[];
    const int k = blockIdx.y, tid = threadIdx.x;
    {
        const float* s1 = Wb + k*4096;  const float* s2 = Wo + k*4096;
        const float* s3 = W1 + k*4096;  const float* s4 = W2 + k*4096;
        for (int i = tid; i < 4096; i += 384) {
            int o = i>>6, c = i&63;
            sm[W_WB + c*64 + o] = s1[i];
            sm[W_WO + c*64 + o] = s2[i];
            sm[W_W1 + c*64 + o] = s3[i];
            sm[W_W2 + c*64 + o] = s4[i];
        }
        const float* sq = Wqkv + k*12288;
        for (int i = tid; i < 12288; i += 384) {
            int o = i>>6, c = i&63;
            sm[W_WQKV + c*192 + o] = sq[i];
        }
        if (tid < 64) {
            sm[B_BB+tid]=bb[k*64+tid];   sm[B_BO+tid]=bo[k*64+tid];
            sm[B_G1+tid]=g1[k*64+tid];   sm[B_BE1+tid]=be1[k*64+tid];
            sm[B_BF1+tid]=bf1[k*64+tid]; sm[B_BF2+tid]=bf2[k*64+tid];
            sm[B_G2+tid]=g2[k*64+tid];   sm[B_BE2+tid]=be2[k*64+tid];
        }
        if (tid < 192) sm[B_BQKV+tid] = bqkv[k*192+tid];
    }
    __syncthreads();

    const float* xdst = xA;
    const float* xsrc = (k==0) ? xB : xA;
    const int* Es = (k==0) ? e_ba : e_aa;
    const int* Ed = Es + NE_;
    float* accum = &g_accum[k][0][0];
    float* cnt = &g_cnt[k][0];

    const int lane = tid & 31, wrp = tid >> 5;
    const int ch0 = 2*lane;
    const int h0 = lane >> 3;                // head owning ch0,ch0+1
    float* scr = sm + SCR + wrp*PF;
    const float* WbT = sm+W_WB;  const float* WqT = sm+W_WQKV;
    const float* WoT = sm+W_WO;  const float* W1T = sm+W_W1;
    const float* W2T = sm+W_W2;

    for (int p = blockIdx.x*NW + wrp; p < NE_/2; p += 148*NW) {
        const int e0 = 2*p, e1 = 2*p+1;
        const int si0 = Es[e0], si1 = Es[e1], di0 = Ed[e0], di1 = Ed[e1];
        float xr[2][2][4], xln[2][2][4];

        // ---- staging: x_dst -> A[c][8] tok0-3 + regs; x_src -> B[c][4] ----
#pragma unroll
        for (int ee = 0; ee < 2; ee++) {
            const float* xd = xdst + (size_t)(ee?di1:di0)*256;
            const float* xp = xsrc + (size_t)(ee?si1:si0)*256;
            float* Ae = scr + ee*EF2;
            float2 dv[4], sv[4];
#pragma unroll
            for (int s = 0; s < 4; s++) {
                dv[s] = *(const float2*)(xd + s*64 + ch0);
                sv[s] = *(const float2*)(xp + s*64 + ch0);
            }
#pragma unroll
            for (int s = 0; s < 4; s++) { xr[ee][0][s]=dv[s].x; xr[ee][1][s]=dv[s].y; }
            *(float4*)(Ae + ch0*8)       = make_float4(dv[0].x,dv[1].x,dv[2].x,dv[3].x);
            *(float4*)(Ae + ch0*8 + 8)   = make_float4(dv[0].y,dv[1].y,dv[2].y,dv[3].y);
            *(float4*)(Ae + 512 + ch0*4) = make_float4(sv[0].x,sv[1].x,sv[2].x,sv[3].x);
            *(float4*)(Ae + 512 + ch0*4 + 4) = make_float4(sv[0].y,sv[1].y,sv[2].y,sv[3].y);
        }
        __syncwarp();

        // ---- b_proj -> A[c][8] tokens 4..7 ----
        {
            float b0f,b1f; upk2(*(const u64*)(sm+B_BB+ch0), b0f,b1f);
            u64 acc[2][2][2];
#pragma unroll
            for (int ee=0; ee<2; ee++) {
                acc[ee][0][0]=acc[ee][0][1]=pk2(b0f,b0f);
                acc[ee][1][0]=acc[ee][1][1]=pk2(b1f,b1f);
            }
            const float* v0p = scr+512; const float* v1p = scr+EF2+512;
#pragma unroll 4
            for (int c = 0; c < 64; c++) {
                float w0,w1; upk2(*(const u64*)(WbT+c*64+ch0), w0,w1);
                u64 w00=pk2(w0,w0), w11=pk2(w1,w1);
                ulonglong2 x0 = *(const ulonglong2*)(v0p + c*4);
                ulonglong2 x1 = *(const ulonglong2*)(v1p + c*4);
                fma2(acc[0][0][0],x0.x,w00); fma2(acc[0][0][1],x0.y,w00);
                fma2(acc[0][1][0],x0.x,w11); fma2(acc[0][1][1],x0.y,w11);
                fma2(acc[1][0][0],x1.x,w00); fma2(acc[1][0][1],x1.y,w00);
                fma2(acc[1][1][0],x1.x,w11); fma2(acc[1][1][1],x1.y,w11);
            }
#pragma unroll
            for (int ee=0; ee<2; ee++) {
                float* Ae = scr + ee*EF2;
                *(u64*)(Ae+ch0*8+4)  = acc[ee][0][0]; *(u64*)(Ae+ch0*8+6)  = acc[ee][0][1];
                *(u64*)(Ae+ch0*8+12) = acc[ee][1][0]; *(u64*)(Ae+ch0*8+14) = acc[ee][1][1];
            }
        }
        __syncwarp();

        // ---- Q pass: q (tokens 0..3) -> Qregion [s][64] ----
        {
            float bqa,bqb; upk2(*(const u64*)(sm+B_BQKV+ch0), bqa,bqb);
            u64 q2[2][2][2];
#pragma unroll
            for (int ee=0; ee<2; ee++) {
                q2[ee][0][0]=q2[ee][0][1]=pk2(bqa,bqa);
                q2[ee][1][0]=q2[ee][1][1]=pk2(bqb,bqb);
            }
#pragma unroll 4
            for (int c = 0; c < 64; c++) {
                float w0,w1; upk2(*(const u64*)(WqT + c*192 + ch0), w0,w1);
                u64 wq0=pk2(w0,w0), wq1=pk2(w1,w1);
#pragma unroll
                for (int ee=0; ee<2; ee++) {
                    ulonglong2 xlo = *(const ulonglong2*)(scr + ee*EF2 + c*8);
                    fma2(q2[ee][0][0],xlo.x,wq0); fma2(q2[ee][0][1],xlo.y,wq0);
                    fma2(q2[ee][1][0],xlo.x,wq1); fma2(q2[ee][1][1],xlo.y,wq1);
                }
            }
#pragma unroll
            for (int ee=0; ee<2; ee++) {
                float* Qe = scr + ee*EF2 + 768;
#pragma unroll
                for (int tp=0; tp<2; tp++) {
                    float qa0,qa1,qb0,qb1;
                    upk2(q2[ee][0][tp], qa0,qa1);
                    upk2(q2[ee][1][tp], qb0,qb1);
                    *(u64*)(Qe + (2*tp)*64 + ch0)   = pk2(qa0,qb0);
                    *(u64*)(Qe + (2*tp+1)*64 + ch0) = pk2(qa1,qb1);
                }
            }
        }

        // ---- V pass: v -> regs only (16 u64 accumulators) ----
        float vv[2][8][2];
        {
            float bva,bvb; upk2(*(const u64*)(sm+B_BQKV+128+ch0), bva,bvb);
            u64 v2[2][2][4];
#pragma unroll
            for (int ee=0; ee<2; ee++)
#pragma unroll
                for (int q=0;q<4;q++) {
                    v2[ee][0][q]=pk2(bva,bva); v2[ee][1][q]=pk2(bvb,bvb);
                }
#pragma unroll 2
            for (int c = 0; c < 64; c++) {
                float v0,v1; upk2(*(const u64*)(WqT + c*192 + 128 + ch0), v0,v1);
                u64 wv0=pk2(v0,v0), wv1=pk2(v1,v1);
#pragma unroll
                for (int ee=0; ee<2; ee++) {
                    const float* xc = scr + ee*EF2 + c*8;
                    ulonglong2 xlo = *(const ulonglong2*)(xc);
                    ulonglong2 xhi = *(const ulonglong2*)(xc+4);
                    fma2(v2[ee][0][0],xlo.x,wv0); fma2(v2[ee][0][1],xlo.y,wv0);
                    fma2(v2[ee][0][2],xhi.x,wv0); fma2(v2[ee][0][3],xhi.y,wv0);
                    fma2(v2[ee][1][0],xlo.x,wv1); fma2(v2[ee][1][1],xlo.y,wv1);
                    fma2(v2[ee][1][2],xhi.x,wv1); fma2(v2[ee][1][3],xhi.y,wv1);
                }
            }
#pragma unroll
            for (int ee=0; ee<2; ee++)
#pragma unroll
                for (int tp=0; tp<4; tp++) {
                    upk2(v2[ee][0][tp], vv[ee][2*tp][0], vv[ee][2*tp+1][0]);
                    upk2(v2[ee][1][tp], vv[ee][2*tp][1], vv[ee][2*tp+1][1]);
                }
        }

        // ---- K pass: k -> A overlay (16 u64 accumulators) ----
        {
            float bka,bkb; upk2(*(const u64*)(sm+B_BQKV+64+ch0), bka,bkb);
            u64 k2[2][2][4];
#pragma unroll
            for (int ee=0; ee<2; ee++)
#pragma unroll
                for (int q=0;q<4;q++) {
                    k2[ee][0][q]=pk2(bka,bka); k2[ee][1][q]=pk2(bkb,bkb);
                }
#pragma unroll 2
            for (int c = 0; c < 64; c++) {
                float k0,k1; upk2(*(const u64*)(WqT + c*192 + 64 + ch0), k0,k1);
                u64 wk0=pk2(k0,k0), wk1=pk2(k1,k1);
#pragma unroll
                for (int ee=0; ee<2; ee++) {
                    const float* xc = scr + ee*EF2 + c*8;
                    ulonglong2 xlo = *(const ulonglong2*)(xc);
                    ulonglong2 xhi = *(const ulonglong2*)(xc+4);
                    fma2(k2[ee][0][0],xlo.x,wk0); fma2(k2[ee][0][1],xlo.y,wk0);
                    fma2(k2[ee][0][2],xhi.x,wk0); fma2(k2[ee][0][3],xhi.y,wk0);
                    fma2(k2[ee][1][0],xlo.x,wk1); fma2(k2[ee][1][1],xlo.y,wk1);
                    fma2(k2[ee][1][2],xhi.x,wk1); fma2(k2[ee][1][3],xhi.y,wk1);
                }
            }
            __syncwarp();   // all xC reads done before K overwrites A
#pragma unroll
            for (int ee=0; ee<2; ee++) {
                float* Ae = scr + ee*EF2;
#pragma unroll
                for (int tp=0; tp<4; tp++) {
                    float ka0,ka1,kb0,kb1;
                    upk2(k2[ee][0][tp], ka0,ka1);
                    upk2(k2[ee][1][tp], kb0,kb1);
                    *(u64*)(Ae + (2*tp)*64 + ch0)   = pk2(ka0,kb0);
                    *(u64*)(Ae + (2*tp+1)*64 + ch0) = pk2(ka1,kb1);
                }
            }
        }
        __syncwarp();

        // ---- scores + softmax: lane = aee*16 + ah*4 + as ----
        float sc[8];
        {
            const int aee = lane>>4, ah = (lane>>2)&3, as = lane&3;
            const float* qr = scr + aee*EF2 + 768 + as*64 + ah*16;
            float qv[16];
            *(float4*)(qv)    = *(const float4*)(qr);
            *(float4*)(qv+4)  = *(const float4*)(qr+4);
            *(float4*)(qv+8)  = *(const float4*)(qr+8);
            *(float4*)(qv+12) = *(const float4*)(qr+12);
            const float* Ka = scr + aee*EF2;
            float mx = -1e30f;
#pragma unroll
            for (int t = 0; t < 8; t++) {
                const float* kr = Ka + t*64 + ah*16;
                float kv[16];
                *(float4*)(kv)    = *(const float4*)(kr);
                *(float4*)(kv+4)  = *(const float4*)(kr+4);
                *(float4*)(kv+8)  = *(const float4*)(kr+8);
                *(float4*)(kv+12) = *(const float4*)(kr+12);
                float d = 0.f;
#pragma unroll
                for (int dd = 0; dd < 16; dd++) d += qv[dd]*kv[dd];
                d *= 0.25f;
                sc[t] = d; mx = fmaxf(mx, d);
            }
            float sum = 0.f;
#pragma unroll
            for (int t = 0; t < 8; t++) { sc[t] = __expf(sc[t]-mx); sum += sc[t]; }
            float inv = 1.0f/sum;
#pragma unroll
            for (int t = 0; t < 8; t++) sc[t] *= inv;
        }
        __syncwarp();   // all K/q reads done before o overlays A

        // ---- o-accum via shfl p-broadcast; v in regs ----
        {
            u64 o2[2][2][2];
#pragma unroll
            for (int ee=0; ee<2; ee++)
#pragma unroll
                for (int j=0;j<2;j++) { o2[ee][j][0]=0ull; o2[ee][j][1]=0ull; }
#pragma unroll
            for (int t = 0; t < 8; t++) {
                float pe[2][4];
#pragma unroll
                for (int ee2=0; ee2<2; ee2++)
#pragma unroll
                    for (int s2=0; s2<4; s2++)
                        pe[ee2][s2] = __shfl_sync(~0u, sc[t], ee2*16 + h0*4 + s2);
#pragma unroll
                for (int ee2=0; ee2<2; ee2++) {
                    u64 pp0 = pk2(pe[ee2][0], pe[ee2][1]);
                    u64 pp1 = pk2(pe[ee2][2], pe[ee2][3]);
                    u64 vd0 = pk2(vv[ee2][t][0], vv[ee2][t][0]);
                    u64 vd1 = pk2(vv[ee2][t][1], vv[ee2][t][1]);
                    fma2(o2[ee2][0][0], pp0, vd0); fma2(o2[ee2][0][1], pp1, vd0);
                    fma2(o2[ee2][1][0], pp0, vd1); fma2(o2[ee2][1][1], pp1, vd1);
                }
            }
#pragma unroll
            for (int ee=0; ee<2; ee++) {
                float* Ae = scr + ee*EF2;
                *(u64*)(Ae + ch0*4)     = o2[ee][0][0];
                *(u64*)(Ae + ch0*4 + 2) = o2[ee][0][1];
                *(u64*)(Ae + ch0*4 + 4) = o2[ee][1][0];
                *(u64*)(Ae + ch0*4 + 6) = o2[ee][1][1];
            }
        }
        __syncwarp();

        // ---- Wo + residual + LN1 -> regs + A[256:512] ([c][4]) ----
        {
            float b0f,b1f; upk2(*(const u64*)(sm+B_BO+ch0), b0f,b1f);
            u64 acc[2][2][2];
#pragma unroll
            for (int ee=0; ee<2; ee++) {
                acc[ee][0][0]=acc[ee][0][1]=pk2(b0f,b0f);
                acc[ee][1][0]=acc[ee][1][1]=pk2(b1f,b1f);
            }
            const float* o0p = scr; const float* o1p = scr+EF2;
#pragma unroll 4
            for (int c = 0; c < 64; c++) {
                float w0,w1; upk2(*(const u64*)(WoT+c*64+ch0), w0,w1);
                u64 w00=pk2(w0,w0), w11=pk2(w1,w1);
                ulonglong2 x0 = *(const ulonglong2*)(o0p + c*4);
                ulonglong2 x1 = *(const ulonglong2*)(o1p + c*4);
                fma2(acc[0][0][0],x0.x,w00); fma2(acc[0][0][1],x0.y,w00);
                fma2(acc[0][1][0],x0.x,w11); fma2(acc[0][1][1],x0.y,w11);
                fma2(acc[1][0][0],x1.x,w00); fma2(acc[1][0][1],x1.y,w00);
                fma2(acc[1][1][0],x1.x,w11); fma2(acc[1][1][1],x1.y,w11);
            }
            float ga,gb,ba,bb2;
            upk2(*(const u64*)(sm+B_G1+ch0), ga,gb);
            upk2(*(const u64*)(sm+B_BE1+ch0), ba,bb2);
#pragma unroll
            for (int ee=0; ee<2; ee++) {
                float a[2][4];
                upk2(acc[ee][0][0],a[0][0],a[0][1]); upk2(acc[ee][0][1],a[0][2],a[0][3]);
                upk2(acc[ee][1][0],a[1][0],a[1][1]); upk2(acc[ee][1][1],a[1][2],a[1][3]);
#pragma unroll
                for (int s = 0; s < 4; s++) {
                    float v0 = a[0][s] + xr[ee][0][s];
                    float v1 = a[1][s] + xr[ee][1][s];
                    lnpair(v0, v1, ga, gb, ba, bb2);
                    xln[ee][0][s]=v0; xln[ee][1][s]=v1;
                }
                float* Xe = scr + ee*EF2 + 256;
                *(u64*)(Xe + ch0*4)     = pk2(xln[ee][0][0],xln[ee][0][1]);
                *(u64*)(Xe + ch0*4 + 2) = pk2(xln[ee][0][2],xln[ee][0][3]);
                *(u64*)(Xe + ch0*4 + 4) = pk2(xln[ee][1][0],xln[ee][1][1]);
                *(u64*)(Xe + ch0*4 + 6) = pk2(xln[ee][1][2],xln[ee][1][3]);
            }
        }
        __syncwarp();

        // ---- FF1: relu -> B region ([f][4]) ----
        {
            float b0f,b1f; upk2(*(const u64*)(sm+B_BF1+ch0), b0f,b1f);
            u64 acc[2][2][2];
#pragma unroll
            for (int ee=0; ee<2; ee++) {
                acc[ee][0][0]=acc[ee][0][1]=pk2(b0f,b0f);
                acc[ee][1][0]=acc[ee][1][1]=pk2(b1f,b1f);
            }
            const float* x0p = scr+256; const float* x1p = scr+EF2+256;
#pragma unroll 4
            for (int c = 0; c < 64; c++) {
                float w0,w1; upk2(*(const u64*)(W1T+c*64+ch0), w0,w1);
                u64 w00=pk2(w0,w0), w11=pk2(w1,w1);
                ulonglong2 x0 = *(const ulonglong2*)(x0p + c*4);
                ulonglong2 x1 = *(const ulonglong2*)(x1p + c*4);
                fma2(acc[0][0][0],x0.x,w00); fma2(acc[0][0][1],x0.y,w00);
                fma2(acc[0][1][0],x0.x,w11); fma2(acc[0][1][1],x0.y,w11);
                fma2(acc[1][0][0],x1.x,w00); fma2(acc[1][0][1],x1.y,w00);
                fma2(acc[1][1][0],x1.x,w11); fma2(acc[1][1][1],x1.y,w11);
            }
#pragma unroll
            for (int ee=0; ee<2; ee++) {
                float* He = scr + ee*EF2 + 512;
                float a,b;
                upk2(acc[ee][0][0],a,b); *(u64*)(He+ch0*4)   = pk2(fmaxf(a,0.f),fmaxf(b,0.f));
                upk2(acc[ee][0][1],a,b); *(u64*)(He+ch0*4+2) = pk2(fmaxf(a,0.f),fmaxf(b,0.f));
                upk2(acc[ee][1][0],a,b); *(u64*)(He+ch0*4+4) = pk2(fmaxf(a,0.f),fmaxf(b,0.f));
                upk2(acc[ee][1][1],a,b); *(u64*)(He+ch0*4+6) = pk2(fmaxf(a,0.f),fmaxf(b,0.f));
            }
        }
        __syncwarp();

        // ---- FF2 + residual + LN2 + scatter ----
        {
            float b0f,b1f; upk2(*(const u64*)(sm+B_BF2+ch0), b0f,b1f);
            u64 acc[2][2][2];
#pragma unroll
            for (int ee=0; ee<2; ee++) {
                acc[ee][0][0]=acc[ee][0][1]=pk2(b0f,b0f);
                acc[ee][1][0]=acc[ee][1][1]=pk2(b1f,b1f);
            }
            const float* h0p = scr+512; const float* h1p = scr+EF2+512;
#pragma unroll 4
            for (int f = 0; f < 64; f++) {
                float w0,w1; upk2(*(const u64*)(W2T+f*64+ch0), w0,w1);
                u64 w00=pk2(w0,w0), w11=pk2(w1,w1);
                ulonglong2 x0 = *(const ulonglong2*)(h0p + f*4);
                ulonglong2 x1 = *(const ulonglong2*)(h1p + f*4);
                fma2(acc[0][0][0],x0.x,w00); fma2(acc[0][0][1],x0.y,w00);
                fma2(acc[0][1][0],x0.x,w11); fma2(acc[0][1][1],x0.y,w11);
                fma2(acc[1][0][0],x1.x,w00); fma2(acc[1][0][1],x1.y,w00);
                fma2(acc[1][1][0],x1.x,w11); fma2(acc[1][1][1],x1.y,w11);
            }
            float ga,gb,ba,bb2;
            upk2(*(const u64*)(sm+B_G2+ch0), ga,gb);
            upk2(*(const u64*)(sm+B_BE2+ch0), ba,bb2);
#pragma unroll
            for (int ee=0; ee<2; ee++) {
                float a[2][4];
                upk2(acc[ee][0][0],a[0][0],a[0][1]); upk2(acc[ee][0][1],a[0][2],a[0][3]);
                upk2(acc[ee][1][0],a[1][0],a[1][1]); upk2(acc[ee][1][1],a[1][2],a[1][3]);
                float* outp = accum + (size_t)(ee?di1:di0)*256;
#pragma unroll
                for (int s = 0; s < 4; s++) {
                    float v0 = a[0][s] + xln[ee][0][s];
                    float v1 = a[1][s] + xln[ee][1][s];
                    lnpair(v0, v1, ga, gb, ba, bb2);
                    red2(outp + s*64 + ch0, v0, v1);
                }
            }
            if (lane == 0) { atomicAdd(cnt+di0, 1.0f); atomicAdd(cnt+di1, 1.0f); }
        }
        __syncwarp();
    }
}

__global__ void __launch_bounds__(256) final_kernel(
    const float* __restrict__ Wout, const float* __restrict__ bout,
    float* __restrict__ out)
{
    __shared__ float WoT[2048];
    __shared__ float xs[8][64];
    const int tid = threadIdx.x;
    for (int i = tid; i < 2048; i += 256) {
        int o = i>>6, c = i&63;
        WoT[c*32+o] = Wout[i];
    }
    __syncthreads();
    const int wrp = tid>>5, lane = tid&31;
    const int n = blockIdx.x*8 + wrp;
    if (n >= NA_) return;
    float c0 = g_cnt[0][n], c1 = g_cnt[1][n];
    float i0 = (c0>0.f) ? 0.5f/c0 : 0.f;
    float i1 = (c1>0.f) ? 0.5f/c1 : 0.f;
    const float* a0p = &g_accum[0][n][0];
    const float* a1p = &g_accum[1][n][0];
    float s0 = 0.f, s1 = 0.f;
#pragma unroll
    for (int t = 0; t < 4; t++) {
        s0 += a0p[t*64+lane]*i0 + a1p[t*64+lane]*i1;
        s1 += a0p[t*64+32+lane]*i0 + a1p[t*64+32+lane]*i1;
    }
    xs[wrp][lane] = s0; xs[wrp][lane+32] = s1;
    __syncwarp();
    float lg = 4.0f*bout[lane];
#pragma unroll
    for (int c = 0; c < 64; c++) lg += xs[wrp][c]*WoT[c*32+lane];
    float m = lg;
#pragma unroll
    for (int o = 16; o; o >>= 1) m = fmaxf(m, __shfl_xor_sync(~0u, m, o));
    float ev = __expf(lg - m);
    float sum = ev;
#pragma unroll
    for (int o = 16; o; o >>= 1) sum += __shfl_xor_sync(~0u, sum, o);
    out[(size_t)n*32 + lane] = ev/sum;
}

extern "C" void kernel_launch(void* const* d_in, const int* in_sizes, int n_in,
                              void* d_out, int out_size) {
    const float* xA   = (const float*)d_in[0];
    const float* xB   = (const float*)d_in[1];
    const int*   e_ba = (const int*)d_in[2];
    const int*   e_aa = (const int*)d_in[3];
    const float* Wb   = (const float*)d_in[4];
    const float* bb   = (const float*)d_in[5];
    const float* Wqkv = (const float*)d_in[6];
    const float* bqkv = (const float*)d_in[7];
    const float* Wo   = (const float*)d_in[8];
    const float* bo   = (const float*)d_in[9];
    const float* g1   = (const float*)d_in[10];
    const float* be1  = (const float*)d_in[11];
    const float* W1   = (const float*)d_in[12];
    const float* bf1  = (const float*)d_in[13];
    const float* W2   = (const float*)d_in[14];
    const float* bf2  = (const float*)d_in[15];
    const float* g2   = (const float*)d_in[16];
    const float* be2  = (const float*)d_in[17];
    const float* Wout = (const float*)d_in[18];
    const float* bout = (const float*)d_in[19];

    cudaFuncSetAttribute(edge_kernel,
                         cudaFuncAttributeMaxDynamicSharedMemorySize, SMEM_BYTES);
    // g_accum zero at module load; zero_kernel at END primes next call.
    edge_kernel<<<dim3(148,2), 384, SMEM_BYTES>>>(
        xA, xB, e_ba, e_aa, Wb, bb, Wqkv, bqkv, Wo, bo,
        g1, be1, W1, bf1, W2, bf2, g2, be2);
    final_kernel<<<(NA_+7)/8, 256>>>(Wout, bout, (float*)d_out);
    zero_kernel<<<1024, 256>>>();
}

// round 10
// speedup vs baseline: 1.2924x; 1.0156x over previous
#include <cuda_runtime.h>
typedef unsigned long long u64;
#define NA_ 40000
#define NE_ 150000

#define W_WB 0
#define W_WQKV 4096
#define W_WO 16384
#define W_W1 20480
#define W_W2 24576
#define B_BB 28672
#define B_BQKV (B_BB+64)
#define B_BO (B_BB+256)
#define B_G1 (B_BB+320)
#define B_BE1 (B_BB+384)
#define B_BF1 (B_BB+448)
#define B_BF2 (B_BB+512)
#define B_G2 (B_BB+576)
#define B_BE2 (B_BB+640)
#define SCR 29376
// per-edge region EFE=784 floats:
//  A [0:512):   xC [half][64][4] (half0=c*4, half1=256+c*4)
//               -> K[8][64] overlay -> o[64][4]@[0:256) + x'[64][4]@[256:512)
//  B [512:784): src[64][4] -> Q[4][68] -> hidden[64][4]
#define EFE 784
#define WF (2*EFE)
#define NW 12
#define SMEM_BYTES ((SCR+NW*WF)*4)   // 192768 B

__device__ __align__(16) float g_accum[2][NA_][256];
__device__ __align__(16) float g_cnt[2][NA_];

__global__ void zero_kernel() {
    float4* a = (float4*)&g_accum[0][0][0];
    const int n4 = 2*NA_*64;
    for (int i = blockIdx.x*blockDim.x+threadIdx.x; i < n4; i += gridDim.x*blockDim.x)
        a[i] = make_float4(0.f,0.f,0.f,0.f);
    float4* c = (float4*)&g_cnt[0][0];
    for (int i = blockIdx.x*blockDim.x+threadIdx.x; i < 2*NA_/4; i += gridDim.x*blockDim.x)
        c[i] = make_float4(0.f,0.f,0.f,0.f);
}

__device__ __forceinline__ u64 pk2(float a, float b) {
    u64 r; asm("mov.b64 %0,{%1,%2};" : "=l"(r) : "f"(a), "f"(b)); return r;
}
__device__ __forceinline__ void upk2(u64 v, float& a, float& b) {
    asm("mov.b64 {%0,%1},%2;" : "=f"(a), "=f"(b) : "l"(v));
}
__device__ __forceinline__ void fma2(u64& d, u64 a, u64 b) {
    asm("fma.rn.f32x2 %0,%1,%2,%0;" : "+l"(d) : "l"(a), "l"(b));
}
__device__ __forceinline__ void lnpair(float& v0, float& v1, float ga, float gb,
                                       float ba, float bb2) {
    float sum = v0+v1, sq = v0*v0+v1*v1;
#pragma unroll
    for (int o = 16; o; o >>= 1) {
        sum += __shfl_xor_sync(~0u, sum, o);
        sq  += __shfl_xor_sync(~0u, sq, o);
    }
    float m = sum*(1.f/64.f);
    float rs = rsqrtf(sq*(1.f/64.f)-m*m+1e-5f);
    v0 = (v0-m)*rs*ga+ba; v1 = (v1-m)*rs*gb+bb2;
}
__device__ __forceinline__ void red2(float* p, float a, float b) {
    asm volatile("red.global.add.v2.f32 [%0],{%1,%2};" :: "l"(p), "f"(a), "f"(b) : "memory");
}

__global__ void __launch_bounds__(384,1) edge_kernel(
    const float* __restrict__ xA, const float* __restrict__ xB,
    const int* __restrict__ e_ba, const int* __restrict__ e_aa,
    const float* __restrict__ Wb, const float* __restrict__ bb,
    const float* __restrict__ Wqkv, const float* __restrict__ bqkv,
    const float* __restrict__ Wo, const float* __restrict__ bo,
    const float* __restrict__ g1, const float* __restrict__ be1,
    const float* __restrict__ W1, const float* __restrict__ bf1,
    const float* __restrict__ W2, const float* __restrict__ bf2,
    const float* __restrict__ g2, const float* __restrict__ be2)
{
    extern __shared__ float sm[];
    const int k = blockIdx.y, tid = threadIdx.x;
    {
        const float* s1 = Wb + k*4096;  const float* s2 = Wo + k*4096;
        const float* s3 = W1 + k*4096;  const float* s4 = W2 + k*4096;
        for (int i = tid; i < 4096; i += 384) {
            int o = i>>6, c = i&63;
            sm[W_WB + c*64 + o] = s1[i];
            sm[W_WO + c*64 + o] = s2[i];
            sm[W_W1 + c*64 + o] = s3[i];
            sm[W_W2 + c*64 + o] = s4[i];
        }
        const float* sq = Wqkv + k*12288;
        for (int i = tid; i < 12288; i += 384) {
            int o = i>>6, c = i&63;
            sm[W_WQKV + c*192 + o] = sq[i];
        }
        if (tid < 64) {
            sm[B_BB+tid]=bb[k*64+tid];   sm[B_BO+tid]=bo[k*64+tid];
            sm[B_G1+tid]=g1[k*64+tid];   sm[B_BE1+tid]=be1[k*64+tid];
            sm[B_BF1+tid]=bf1[k*64+tid]; sm[B_BF2+tid]=bf2[k*64+tid];
            sm[B_G2+tid]=g2[k*64+tid];   sm[B_BE2+tid]=be2[k*64+tid];
        }
        if (tid < 192) sm[B_BQKV+tid] = bqkv[k*192+tid];
    }
    __syncthreads();

    const float* xdst = xA;
    const float* xsrc = (k==0) ? xB : xA;
    const int* Es = (k==0) ? e_ba : e_aa;
    const int* Ed = Es + NE_;
    float* accum = &g_accum[k][0][0];
    float* cnt = &g_cnt[k][0];

    const int lane = tid & 31, wrp = tid >> 5;
    const int chA = lane, chB = lane + 32;   // conflict-free channel split
    const int hLo = lane >> 4;               // head of chA; head of chB = hLo+2
    float* scr = sm + SCR + wrp*WF;
    const float* WbT = sm+W_WB;  const float* WqT = sm+W_WQKV;
    const float* WoT = sm+W_WO;  const float* W1T = sm+W_W1;
    const float* W2T = sm+W_W2;

    for (int p = blockIdx.x*NW + wrp; p < NE_/2; p += 148*NW) {
        const int e0 = 2*p, e1 = 2*p+1;
        const int si0 = Es[e0], si1 = Es[e1], di0 = Ed[e0], di1 = Ed[e1];
        float xr[2][2][4], xln[2][2][4];

        // ---- staging: conflict-free float4 rows ----
#pragma unroll
        for (int ee = 0; ee < 2; ee++) {
            const float* xd = xdst + (size_t)(ee?di1:di0)*256;
            const float* xp = xsrc + (size_t)(ee?si1:si0)*256;
            float* Ae = scr + ee*EFE;
            float* Be = Ae + 512;
            float dA[4], dB[4], sA[4], sB[4];
#pragma unroll
            for (int s = 0; s < 4; s++) {
                dA[s] = xd[s*64+chA]; dB[s] = xd[s*64+chB];
                sA[s] = xp[s*64+chA]; sB[s] = xp[s*64+chB];
                xr[ee][0][s] = dA[s]; xr[ee][1][s] = dB[s];
            }
            *(float4*)(Ae + chA*4) = make_float4(dA[0],dA[1],dA[2],dA[3]);
            *(float4*)(Ae + chB*4) = make_float4(dB[0],dB[1],dB[2],dB[3]);
            *(float4*)(Be + chA*4) = make_float4(sA[0],sA[1],sA[2],sA[3]);
            *(float4*)(Be + chB*4) = make_float4(sB[0],sB[1],sB[2],sB[3]);
        }
        __syncwarp();

        // ---- b_proj -> xC half1 ----
        {
            float b0f = sm[B_BB+chA], b1f = sm[B_BB+chB];
            u64 acc[2][2][2];
#pragma unroll
            for (int ee=0; ee<2; ee++) {
                acc[ee][0][0]=acc[ee][0][1]=pk2(b0f,b0f);
                acc[ee][1][0]=acc[ee][1][1]=pk2(b1f,b1f);
            }
            const float* B0 = scr+512; const float* B1 = scr+EFE+512;
#pragma unroll 4
            for (int c = 0; c < 64; c++) {
                float w0 = WbT[c*64+chA], w1 = WbT[c*64+chB];
                u64 w00=pk2(w0,w0), w11=pk2(w1,w1);
                ulonglong2 x0 = *(const ulonglong2*)(B0 + c*4);
                ulonglong2 x1 = *(const ulonglong2*)(B1 + c*4);
                fma2(acc[0][0][0],x0.x,w00); fma2(acc[0][0][1],x0.y,w00);
                fma2(acc[0][1][0],x0.x,w11); fma2(acc[0][1][1],x0.y,w11);
                fma2(acc[1][0][0],x1.x,w00); fma2(acc[1][0][1],x1.y,w00);
                fma2(acc[1][1][0],x1.x,w11); fma2(acc[1][1][1],x1.y,w11);
            }
#pragma unroll
            for (int ee=0; ee<2; ee++) {
                float* Ah = scr + ee*EFE + 256;
                float a0,a1,a2,a3;
                upk2(acc[ee][0][0],a0,a1); upk2(acc[ee][0][1],a2,a3);
                *(float4*)(Ah + chA*4) = make_float4(a0,a1,a2,a3);
                upk2(acc[ee][1][0],a0,a1); upk2(acc[ee][1][1],a2,a3);
                *(float4*)(Ah + chB*4) = make_float4(a0,a1,a2,a3);
            }
        }
        __syncwarp();

        // ---- Q pass: q (tokens 0..3) -> Q[4][68] over B ----
        {
            float bqa = sm[B_BQKV+chA], bqb = sm[B_BQKV+chB];
            u64 q2[2][2][2];
#pragma unroll
            for (int ee=0; ee<2; ee++) {
                q2[ee][0][0]=q2[ee][0][1]=pk2(bqa,bqa);
                q2[ee][1][0]=q2[ee][1][1]=pk2(bqb,bqb);
            }
#pragma unroll 4
            for (int c = 0; c < 64; c++) {
                float w0 = WqT[c*192+chA], w1 = WqT[c*192+chB];
                u64 wq0=pk2(w0,w0), wq1=pk2(w1,w1);
#pragma unroll
                for (int ee=0; ee<2; ee++) {
                    ulonglong2 xlo = *(const ulonglong2*)(scr + ee*EFE + c*4);
                    fma2(q2[ee][0][0],xlo.x,wq0); fma2(q2[ee][0][1],xlo.y,wq0);
                    fma2(q2[ee][1][0],xlo.x,wq1); fma2(q2[ee][1][1],xlo.y,wq1);
                }
            }
#pragma unroll
            for (int ee=0; ee<2; ee++) {
                float* Qe = scr + ee*EFE + 512;
#pragma unroll
                for (int tp=0; tp<2; tp++) {
                    float a,b;
                    upk2(q2[ee][0][tp],a,b);
                    Qe[(2*tp)*68+chA]=a; Qe[(2*tp+1)*68+chA]=b;
                    upk2(q2[ee][1][tp],a,b);
                    Qe[(2*tp)*68+chB]=a; Qe[(2*tp+1)*68+chB]=b;
                }
            }
        }

        // ---- V pass: v -> regs ----
        float vv[2][8][2];
        {
            float bva = sm[B_BQKV+128+chA], bvb = sm[B_BQKV+128+chB];
            u64 v2[2][2][4];
#pragma unroll
            for (int ee=0; ee<2; ee++)
#pragma unroll
                for (int q=0;q<4;q++) {
                    v2[ee][0][q]=pk2(bva,bva); v2[ee][1][q]=pk2(bvb,bvb);
                }
#pragma unroll 2
            for (int c = 0; c < 64; c++) {
                float v0 = WqT[c*192+128+chA], v1 = WqT[c*192+128+chB];
                u64 wv0=pk2(v0,v0), wv1=pk2(v1,v1);
#pragma unroll
                for (int ee=0; ee<2; ee++) {
                    ulonglong2 xlo = *(const ulonglong2*)(scr + ee*EFE + c*4);
                    ulonglong2 xhi = *(const ulonglong2*)(scr + ee*EFE + 256 + c*4);
                    fma2(v2[ee][0][0],xlo.x,wv0); fma2(v2[ee][0][1],xlo.y,wv0);
                    fma2(v2[ee][0][2],xhi.x,wv0); fma2(v2[ee][0][3],xhi.y,wv0);
                    fma2(v2[ee][1][0],xlo.x,wv1); fma2(v2[ee][1][1],xlo.y,wv1);
                    fma2(v2[ee][1][2],xhi.x,wv1); fma2(v2[ee][1][3],xhi.y,wv1);
                }
            }
#pragma unroll
            for (int ee=0; ee<2; ee++)
#pragma unroll
                for (int tp=0; tp<4; tp++) {
                    upk2(v2[ee][0][tp], vv[ee][2*tp][0], vv[ee][2*tp+1][0]);
                    upk2(v2[ee][1][tp], vv[ee][2*tp][1], vv[ee][2*tp+1][1]);
                }
        }

        // ---- K pass: k -> A overlay [8][64] ----
        {
            float bka = sm[B_BQKV+64+chA], bkb = sm[B_BQKV+64+chB];
            u64 k2[2][2][4];
#pragma unroll
            for (int ee=0; ee<2; ee++)
#pragma unroll
                for (int q=0;q<4;q++) {
                    k2[ee][0][q]=pk2(bka,bka); k2[ee][1][q]=pk2(bkb,bkb);
                }
#pragma unroll 2
            for (int c = 0; c < 64; c++) {
                float k0 = WqT[c*192+64+chA], k1 = WqT[c*192+64+chB];
                u64 wk0=pk2(k0,k0), wk1=pk2(k1,k1);
#pragma unroll
                for (int ee=0; ee<2; ee++) {
                    ulonglong2 xlo = *(const ulonglong2*)(scr + ee*EFE + c*4);
                    ulonglong2 xhi = *(const ulonglong2*)(scr + ee*EFE + 256 + c*4);
                    fma2(k2[ee][0][0],xlo.x,wk0); fma2(k2[ee][0][1],xlo.y,wk0);
                    fma2(k2[ee][0][2],xhi.x,wk0); fma2(k2[ee][0][3],xhi.y,wk0);
                    fma2(k2[ee][1][0],xlo.x,wk1); fma2(k2[ee][1][1],xlo.y,wk1);
                    fma2(k2[ee][1][2],xhi.x,wk1); fma2(k2[ee][1][3],xhi.y,wk1);
                }
            }
            __syncwarp();   // all xC reads done before K overwrites A
#pragma unroll
            for (int ee=0; ee<2; ee++) {
                float* Ka = scr + ee*EFE;
#pragma unroll
                for (int tp=0; tp<4; tp++) {
                    float a,b;
                    upk2(k2[ee][0][tp],a,b);
                    Ka[(2*tp)*64+chA]=a; Ka[(2*tp+1)*64+chA]=b;
                    upk2(k2[ee][1][tp],a,b);
                    Ka[(2*tp)*64+chB]=a; Ka[(2*tp+1)*64+chB]=b;
                }
            }
        }
        __syncwarp();

        // ---- scores + softmax: lane = aee*16 + ah*4 + as ----
        float sc[8];
        {
            const int aee = lane>>4, ah = (lane>>2)&3, as = lane&3;
            const float* qr = scr + aee*EFE + 512 + as*68 + ah*16;
            float qv[16];
            *(float4*)(qv)    = *(const float4*)(qr);
            *(float4*)(qv+4)  = *(const float4*)(qr+4);
            *(float4*)(qv+8)  = *(const float4*)(qr+8);
            *(float4*)(qv+12) = *(const float4*)(qr+12);
            const float* Ka = scr + aee*EFE;
            float mx = -1e30f;
#pragma unroll
            for (int t = 0; t < 8; t++) {
                const float* kr = Ka + t*64 + ah*16;
                float kv[16];
                *(float4*)(kv)    = *(const float4*)(kr);
                *(float4*)(kv+4)  = *(const float4*)(kr+4);
                *(float4*)(kv+8)  = *(const float4*)(kr+8);
                *(float4*)(kv+12) = *(const float4*)(kr+12);
                float d = 0.f;
#pragma unroll
                for (int dd = 0; dd < 16; dd++) d += qv[dd]*kv[dd];
                d *= 0.25f;
                sc[t] = d; mx = fmaxf(mx, d);
            }
            float sum = 0.f;
#pragma unroll
            for (int t = 0; t < 8; t++) { sc[t] = __expf(sc[t]-mx); sum += sc[t]; }
            float inv = 1.0f/sum;
#pragma unroll
            for (int t = 0; t < 8; t++) sc[t] *= inv;
        }
        __syncwarp();   // all K/q reads done before o overlays A

        // ---- o-accum via shfl p-broadcast; v in regs ----
        {
            u64 o2[2][2][2];
#pragma unroll
            for (int ee=0; ee<2; ee++)
#pragma unroll
                for (int j=0;j<2;j++) { o2[ee][j][0]=0ull; o2[ee][j][1]=0ull; }
#pragma unroll
            for (int t = 0; t < 8; t++) {
                float pA[2][4], pB[2][4];
#pragma unroll
                for (int ee2=0; ee2<2; ee2++)
#pragma unroll
                    for (int s2=0; s2<4; s2++) {
                        pA[ee2][s2] = __shfl_sync(~0u, sc[t], ee2*16 + hLo*4 + s2);
                        pB[ee2][s2] = __shfl_sync(~0u, sc[t], ee2*16 + (hLo+2)*4 + s2);
                    }
#pragma unroll
                for (int ee2=0; ee2<2; ee2++) {
                    u64 ppA0 = pk2(pA[ee2][0], pA[ee2][1]);
                    u64 ppA1 = pk2(pA[ee2][2], pA[ee2][3]);
                    u64 ppB0 = pk2(pB[ee2][0], pB[ee2][1]);
                    u64 ppB1 = pk2(pB[ee2][2], pB[ee2][3]);
                    u64 vdA = pk2(vv[ee2][t][0], vv[ee2][t][0]);
                    u64 vdB = pk2(vv[ee2][t][1], vv[ee2][t][1]);
                    fma2(o2[ee2][0][0], ppA0, vdA); fma2(o2[ee2][0][1], ppA1, vdA);
                    fma2(o2[ee2][1][0], ppB0, vdB); fma2(o2[ee2][1][1], ppB1, vdB);
                }
            }
#pragma unroll
            for (int ee=0; ee<2; ee++) {
                float* Ae = scr + ee*EFE;
                float a0,a1,a2,a3;
                upk2(o2[ee][0][0],a0,a1); upk2(o2[ee][0][1],a2,a3);
                *(float4*)(Ae + chA*4) = make_float4(a0,a1,a2,a3);
                upk2(o2[ee][1][0],a0,a1); upk2(o2[ee][1][1],a2,a3);
                *(float4*)(Ae + chB*4) = make_float4(a0,a1,a2,a3);
            }
        }
        __syncwarp();

        // ---- Wo + residual + LN1 -> regs + x'[64][4]@A[256:512) ----
        {
            float b0f = sm[B_BO+chA], b1f = sm[B_BO+chB];
            u64 acc[2][2][2];
#pragma unroll
            for (int ee=0; ee<2; ee++) {
                acc[ee][0][0]=acc[ee][0][1]=pk2(b0f,b0f);
                acc[ee][1][0]=acc[ee][1][1]=pk2(b1f,b1f);
            }
            const float* o0p = scr; const float* o1p = scr+EFE;
#pragma unroll 4
            for (int c = 0; c < 64; c++) {
                float w0 = WoT[c*64+chA], w1 = WoT[c*64+chB];
                u64 w00=pk2(w0,w0), w11=pk2(w1,w1);
                ulonglong2 x0 = *(const ulonglong2*)(o0p + c*4);
                ulonglong2 x1 = *(const ulonglong2*)(o1p + c*4);
                fma2(acc[0][0][0],x0.x,w00); fma2(acc[0][0][1],x0.y,w00);
                fma2(acc[0][1][0],x0.x,w11); fma2(acc[0][1][1],x0.y,w11);
                fma2(acc[1][0][0],x1.x,w00); fma2(acc[1][0][1],x1.y,w00);
                fma2(acc[1][1][0],x1.x,w11); fma2(acc[1][1][1],x1.y,w11);
            }
            float ga = sm[B_G1+chA], gb = sm[B_G1+chB];
            float ba = sm[B_BE1+chA], bb2 = sm[B_BE1+chB];
#pragma unroll
            for (int ee=0; ee<2; ee++) {
                float a[2][4];
                upk2(acc[ee][0][0],a[0][0],a[0][1]); upk2(acc[ee][0][1],a[0][2],a[0][3]);
                upk2(acc[ee][1][0],a[1][0],a[1][1]); upk2(acc[ee][1][1],a[1][2],a[1][3]);
#pragma unroll
                for (int s = 0; s < 4; s++) {
                    float v0 = a[0][s] + xr[ee][0][s];
                    float v1 = a[1][s] + xr[ee][1][s];
                    lnpair(v0, v1, ga, gb, ba, bb2);
                    xln[ee][0][s]=v0; xln[ee][1][s]=v1;
                }
                float* Xe = scr + ee*EFE + 256;
                *(float4*)(Xe + chA*4) = make_float4(xln[ee][0][0],xln[ee][0][1],
                                                    xln[ee][0][2],xln[ee][0][3]);
                *(float4*)(Xe + chB*4) = make_float4(xln[ee][1][0],xln[ee][1][1],
                                                    xln[ee][1][2],xln[ee][1][3]);
            }
        }
        __syncwarp();

        // ---- FF1: relu -> hidden[64][4]@B ----
        {
            float b0f = sm[B_BF1+chA], b1f = sm[B_BF1+chB];
            u64 acc[2][2][2];
#pragma unroll
            for (int ee=0; ee<2; ee++) {
                acc[ee][0][0]=acc[ee][0][1]=pk2(b0f,b0f);
                acc[ee][1][0]=acc[ee][1][1]=pk2(b1f,b1f);
            }
            const float* x0p = scr+256; const float* x1p = scr+EFE+256;
#pragma unroll 4
            for (int c = 0; c < 64; c++) {
                float w0 = W1T[c*64+chA], w1 = W1T[c*64+chB];
                u64 w00=pk2(w0,w0), w11=pk2(w1,w1);
                ulonglong2 x0 = *(const ulonglong2*)(x0p + c*4);
                ulonglong2 x1 = *(const ulonglong2*)(x1p + c*4);
                fma2(acc[0][0][0],x0.x,w00); fma2(acc[0][0][1],x0.y,w00);
                fma2(acc[0][1][0],x0.x,w11); fma2(acc[0][1][1],x0.y,w11);
                fma2(acc[1][0][0],x1.x,w00); fma2(acc[1][0][1],x1.y,w00);
                fma2(acc[1][1][0],x1.x,w11); fma2(acc[1][1][1],x1.y,w11);
            }
#pragma unroll
            for (int ee=0; ee<2; ee++) {
                float* He = scr + ee*EFE + 512;
                float a0,a1,a2,a3;
                upk2(acc[ee][0][0],a0,a1); upk2(acc[ee][0][1],a2,a3);
                *(float4*)(He + chA*4) = make_float4(fmaxf(a0,0.f),fmaxf(a1,0.f),
                                                    fmaxf(a2,0.f),fmaxf(a3,0.f));
                upk2(acc[ee][1][0],a0,a1); upk2(acc[ee][1][1],a2,a3);
                *(float4*)(He + chB*4) = make_float4(fmaxf(a0,0.f),fmaxf(a1,0.f),
                                                    fmaxf(a2,0.f),fmaxf(a3,0.f));
            }
        }
        __syncwarp();

        // ---- FF2 + residual + LN2 + scatter (paired accum layout) ----
        {
            float b0f = sm[B_BF2+chA], b1f = sm[B_BF2+chB];
            u64 acc[2][2][2];
#pragma unroll
            for (int ee=0; ee<2; ee++) {
                acc[ee][0][0]=acc[ee][0][1]=pk2(b0f,b0f);
                acc[ee][1][0]=acc[ee][1][1]=pk2(b1f,b1f);
            }
            const float* h0p = scr+512; const float* h1p = scr+EFE+512;
#pragma unroll 4
            for (int f = 0; f < 64; f++) {
                float w0 = W2T[f*64+chA], w1 = W2T[f*64+chB];
                u64 w00=pk2(w0,w0), w11=pk2(w1,w1);
                ulonglong2 x0 = *(const ulonglong2*)(h0p + f*4);
                ulonglong2 x1 = *(const ulonglong2*)(h1p + f*4);
                fma2(acc[0][0][0],x0.x,w00); fma2(acc[0][0][1],x0.y,w00);
                fma2(acc[0][1][0],x0.x,w11); fma2(acc[0][1][1],x0.y,w11);
                fma2(acc[1][0][0],x1.x,w00); fma2(acc[1][0][1],x1.y,w00);
                fma2(acc[1][1][0],x1.x,w11); fma2(acc[1][1][1],x1.y,w11);
            }
            float ga = sm[B_G2+chA], gb = sm[B_G2+chB];
            float ba = sm[B_BE2+chA], bb2 = sm[B_BE2+chB];
#pragma unroll
            for (int ee=0; ee<2; ee++) {
                float a[2][4];
                upk2(acc[ee][0][0],a[0][0],a[0][1]); upk2(acc[ee][0][1],a[0][2],a[0][3]);
                upk2(acc[ee][1][0],a[1][0],a[1][1]); upk2(acc[ee][1][1],a[1][2],a[1][3]);
                float* outp = accum + (size_t)(ee?di1:di0)*256;
#pragma unroll
                for (int s = 0; s < 4; s++) {
                    float v0 = a[0][s] + xln[ee][0][s];
                    float v1 = a[1][s] + xln[ee][1][s];
                    lnpair(v0, v1, ga, gb, ba, bb2);
                    // paired layout: channel c at s*64 + (c%32)*2 + (c/32)
                    red2(outp + s*64 + lane*2, v0, v1);
                }
            }
            if (lane == 0) { atomicAdd(cnt+di0, 1.0f); atomicAdd(cnt+di1, 1.0f); }
        }
        __syncwarp();
    }
}

__global__ void __launch_bounds__(256) final_kernel(
    const float* __restrict__ Wout, const float* __restrict__ bout,
    float* __restrict__ out)
{
    __shared__ float WoT[2048];
    __shared__ float xs[8][64];
    const int tid = threadIdx.x;
    for (int i = tid; i < 2048; i += 256) {
        int o = i>>6, c = i&63;
        WoT[c*32+o] = Wout[i];
    }
    __syncthreads();
    const int wrp = tid>>5, lane = tid&31;
    const int n = blockIdx.x*8 + wrp;
    if (n >= NA_) return;
    float c0 = g_cnt[0][n], c1 = g_cnt[1][n];
    float i0 = (c0>0.f) ? 0.5f/c0 : 0.f;
    float i1 = (c1>0.f) ? 0.5f/c1 : 0.f;
    const float* a0p = &g_accum[0][n][0];
    const float* a1p = &g_accum[1][n][0];
    // paired layout: channel lane at t*64+lane*2, channel lane+32 at +1
    float s0 = 0.f, s1 = 0.f;
#pragma unroll
    for (int t = 0; t < 4; t++) {
        s0 += a0p[t*64+lane*2]  *i0 + a1p[t*64+lane*2]  *i1;
        s1 += a0p[t*64+lane*2+1]*i0 + a1p[t*64+lane*2+1]*i1;
    }
    xs[wrp][lane] = s0; xs[wrp][lane+32] = s1;
    __syncwarp();
    float lg = 4.0f*bout[lane];
#pragma unroll
    for (int c = 0; c < 64; c++) lg += xs[wrp][c]*WoT[c*32+lane];
    float m = lg;
#pragma unroll
    for (int o = 16; o; o >>= 1) m = fmaxf(m, __shfl_xor_sync(~0u, m, o));
    float ev = __expf(lg - m);
    float sum = ev;
#pragma unroll
    for (int o = 16; o; o >>= 1) sum += __shfl_xor_sync(~0u, sum, o);
    out[(size_t)n*32 + lane] = ev/sum;
}

extern "C" void kernel_launch(void* const* d_in, const int* in_sizes, int n_in,
                              void* d_out, int out_size) {
    const float* xA   = (const float*)d_in[0];
    const float* xB   = (const float*)d_in[1];
    const int*   e_ba = (const int*)d_in[2];
    const int*   e_aa = (const int*)d_in[3];
    const float* Wb   = (const float*)d_in[4];
    const float* bb   = (const float*)d_in[5];
    const float* Wqkv = (const float*)d_in[6];
    const float* bqkv = (const float*)d_in[7];
    const float* Wo   = (const float*)d_in[8];
    const float* bo   = (const float*)d_in[9];
    const float* g1   = (const float*)d_in[10];
    const float* be1  = (const float*)d_in[11];
    const float* W1   = (const float*)d_in[12];
    const float* bf1  = (const float*)d_in[13];
    const float* W2   = (const float*)d_in[14];
    const float* bf2  = (const float*)d_in[15];
    const float* g2   = (const float*)d_in[16];
    const float* be2  = (const float*)d_in[17];
    const float* Wout = (const float*)d_in[18];
    const float* bout = (const float*)d_in[19];

    cudaFuncSetAttribute(edge_kernel,
                         cudaFuncAttributeMaxDynamicSharedMemorySize, SMEM_BYTES);
    // g_accum zero at module load; zero_kernel at END primes next call.
    edge_kernel<<<dim3(148,2), 384, SMEM_BYTES>>>(
        xA, xB, e_ba, e_aa, Wb, bb, Wqkv, bqkv, Wo, bo,
        g1, be1, W1, bf1, W2, bf2, g2, be2);
    final_kernel<<<(NA_+7)/8, 256>>>(Wout, bout, (float*)d_out);
    zero_kernel<<<1024, 256>>>();
}

// round 12
// speedup vs baseline: 1.3005x; 1.0063x over previous
#include <cuda_runtime.h>
typedef unsigned long long u64;
#define NA_ 40000
#define NE_ 150000

#define W_WB 0
#define W_WQKV 4096
#define W_WO 16384
#define W_W1 20480
#define W_W2 24576
#define B_BB 28672
#define B_BQKV (B_BB+64)
#define B_BO (B_BB+256)
#define B_G1 (B_BB+320)
#define B_BE1 (B_BB+384)
#define B_BF1 (B_BB+448)
#define B_BF2 (B_BB+512)
#define B_G2 (B_BB+576)
#define B_BE2 (B_BB+640)
#define SCR 29376
// per-edge region EFE=784 floats:
//  A [0:512):   xC [half][64][4] -> K[8][64] overlay -> o[64][4]@[0:256)+x'[64][4]@[256:512)
//  B [512:784): src[64][4] -> Q[4][68] -> hidden[64][4]
#define EFE 784
#define WF (2*EFE)
#define NW 12
#define SMEM_BYTES ((SCR+NW*WF)*4)   // 192768 B

__device__ __align__(16) float g_accum[2][NA_][256];
__device__ __align__(16) float g_cnt[2][NA_];

__global__ void zero_kernel() {
    float4* a = (float4*)&g_accum[0][0][0];
    const int n4 = 2*NA_*64;
    for (int i = blockIdx.x*blockDim.x+threadIdx.x; i < n4; i += gridDim.x*blockDim.x)
        a[i] = make_float4(0.f,0.f,0.f,0.f);
    float4* c = (float4*)&g_cnt[0][0];
    for (int i = blockIdx.x*blockDim.x+threadIdx.x; i < 2*NA_/4; i += gridDim.x*blockDim.x)
        c[i] = make_float4(0.f,0.f,0.f,0.f);
}

__device__ __forceinline__ u64 pk2(float a, float b) {
    u64 r; asm("mov.b64 %0,{%1,%2};" : "=l"(r) : "f"(a), "f"(b)); return r;
}
__device__ __forceinline__ void upk2(u64 v, float& a, float& b) {
    asm("mov.b64 {%0,%1},%2;" : "=f"(a), "=f"(b) : "l"(v));
}
__device__ __forceinline__ void fma2(u64& d, u64 a, u64 b) {
    asm("fma.rn.f32x2 %0,%1,%2,%0;" : "+l"(d) : "l"(a), "l"(b));
}
__device__ __forceinline__ void lnpair(float& v0, float& v1, float ga, float gb,
                                       float ba, float bb2) {
    float sum = v0+v1, sq = v0*v0+v1*v1;
#pragma unroll
    for (int o = 16; o; o >>= 1) {
        sum += __shfl_xor_sync(~0u, sum, o);
        sq  += __shfl_xor_sync(~0u, sq, o);
    }
    float m = sum*(1.f/64.f);
    float rs = rsqrtf(sq*(1.f/64.f)-m*m+1e-5f);
    v0 = (v0-m)*rs*ga+ba; v1 = (v1-m)*rs*gb+bb2;
}
__device__ __forceinline__ void red2(float* p, float a, float b) {
    asm volatile("red.global.add.v2.f32 [%0],{%1,%2};" :: "l"(p), "f"(a), "f"(b) : "memory");
}

__global__ void __launch_bounds__(384,1) edge_kernel(
    const float* __restrict__ xA, const float* __restrict__ xB,
    const int* __restrict__ e_ba, const int* __restrict__ e_aa,
    const float* __restrict__ Wb, const float* __restrict__ bb,
    const float* __restrict__ Wqkv, const float* __restrict__ bqkv,
    const float* __restrict__ Wo, const float* __restrict__ bo,
    const float* __restrict__ g1, const float* __restrict__ be1,
    const float* __restrict__ W1, const float* __restrict__ bf1,
    const float* __restrict__ W2, const float* __restrict__ bf2,
    const float* __restrict__ g2, const float* __restrict__ be2)
{
    extern __shared__ float sm[];
    const int k = blockIdx.y, tid = threadIdx.x;
    // ---- weights, paired layout: value for output o at (o%32)*2 + o/32 ----
    {
        const float* s1 = Wb + k*4096;  const float* s2 = Wo + k*4096;
        const float* s3 = W1 + k*4096;  const float* s4 = W2 + k*4096;
        for (int i = tid; i < 4096; i += 384) {
            int o = i>>6, c = i&63;
            int po = ((o&31)<<1) | (o>>5);
            sm[W_WB + c*64 + po] = s1[i];
            sm[W_WO + c*64 + po] = s2[i];
            sm[W_W1 + c*64 + po] = s3[i];
            sm[W_W2 + c*64 + po] = s4[i];
        }
        const float* sq = Wqkv + k*12288;
        for (int i = tid; i < 12288; i += 384) {
            int o = i>>6, c = i&63;      // o in 0..191
            int blk = o>>6, oo = o&63;
            int po = ((oo&31)<<1) | (oo>>5);
            sm[W_WQKV + c*192 + blk*64 + po] = sq[i];
        }
        if (tid < 64) {
            sm[B_BB+tid]=bb[k*64+tid];   sm[B_BO+tid]=bo[k*64+tid];
            sm[B_G1+tid]=g1[k*64+tid];   sm[B_BE1+tid]=be1[k*64+tid];
            sm[B_BF1+tid]=bf1[k*64+tid]; sm[B_BF2+tid]=bf2[k*64+tid];
            sm[B_G2+tid]=g2[k*64+tid];   sm[B_BE2+tid]=be2[k*64+tid];
        }
        if (tid < 192) sm[B_BQKV+tid] = bqkv[k*192+tid];
    }
    __syncthreads();

    const float* xdst = xA;
    const float* xsrc = (k==0) ? xB : xA;
    const int* Es = (k==0) ? e_ba : e_aa;
    const int* Ed = Es + NE_;
    float* accum = &g_accum[k][0][0];
    float* cnt = &g_cnt[k][0];

    const int lane = tid & 31, wrp = tid >> 5;
    const int chA = lane, chB = lane + 32;
    const int hLo = lane >> 4;               // head of chA; head of chB = hLo+2
    const int wl2 = 2*lane;
    float* scr = sm + SCR + wrp*WF;
    const float* WbT = sm+W_WB;  const float* WqT = sm+W_WQKV;
    const float* WoT = sm+W_WO;  const float* W1T = sm+W_W1;
    const float* W2T = sm+W_W2;

    for (int p = blockIdx.x*NW + wrp; p < NE_/2; p += 148*NW) {
        const int e0 = 2*p, e1 = 2*p+1;
        const int si0 = Es[e0], si1 = Es[e1], di0 = Ed[e0], di1 = Ed[e1];
        float xr[2][2][4], xln[2][2][4];

        // ---- staging ----
#pragma unroll
        for (int ee = 0; ee < 2; ee++) {
            const float* xd = xdst + (size_t)(ee?di1:di0)*256;
            const float* xp = xsrc + (size_t)(ee?si1:si0)*256;
            float* Ae = scr + ee*EFE;
            float* Be = Ae + 512;
            float dA[4], dB[4], sA[4], sB[4];
#pragma unroll
            for (int s = 0; s < 4; s++) {
                dA[s] = xd[s*64+chA]; dB[s] = xd[s*64+chB];
                sA[s] = xp[s*64+chA]; sB[s] = xp[s*64+chB];
                xr[ee][0][s] = dA[s]; xr[ee][1][s] = dB[s];
            }
            *(float4*)(Ae + chA*4) = make_float4(dA[0],dA[1],dA[2],dA[3]);
            *(float4*)(Ae + chB*4) = make_float4(dB[0],dB[1],dB[2],dB[3]);
            *(float4*)(Be + chA*4) = make_float4(sA[0],sA[1],sA[2],sA[3]);
            *(float4*)(Be + chB*4) = make_float4(sB[0],sB[1],sB[2],sB[3]);
        }
        __syncwarp();

        // ---- b_proj -> xC half1 ----
        {
            float b0f = sm[B_BB+chA], b1f = sm[B_BB+chB];
            u64 acc[2][2][2];
#pragma unroll
            for (int ee=0; ee<2; ee++) {
                acc[ee][0][0]=acc[ee][0][1]=pk2(b0f,b0f);
                acc[ee][1][0]=acc[ee][1][1]=pk2(b1f,b1f);
            }
            const float* B0 = scr+512; const float* B1 = scr+EFE+512;
#pragma unroll 4
            for (int c = 0; c < 64; c++) {
                float2 wp = *(const float2*)(WbT + c*64 + wl2);
                u64 w00=pk2(wp.x,wp.x), w11=pk2(wp.y,wp.y);
                ulonglong2 x0 = *(const ulonglong2*)(B0 + c*4);
                ulonglong2 x1 = *(const ulonglong2*)(B1 + c*4);
                fma2(acc[0][0][0],x0.x,w00); fma2(acc[0][0][1],x0.y,w00);
                fma2(acc[0][1][0],x0.x,w11); fma2(acc[0][1][1],x0.y,w11);
                fma2(acc[1][0][0],x1.x,w00); fma2(acc[1][0][1],x1.y,w00);
                fma2(acc[1][1][0],x1.x,w11); fma2(acc[1][1][1],x1.y,w11);
            }
#pragma unroll
            for (int ee=0; ee<2; ee++) {
                float* Ah = scr + ee*EFE + 256;
                float a0,a1,a2,a3;
                upk2(acc[ee][0][0],a0,a1); upk2(acc[ee][0][1],a2,a3);
                *(float4*)(Ah + chA*4) = make_float4(a0,a1,a2,a3);
                upk2(acc[ee][1][0],a0,a1); upk2(acc[ee][1][1],a2,a3);
                *(float4*)(Ah + chB*4) = make_float4(a0,a1,a2,a3);
            }
        }
        __syncwarp();

        // ---- V+Q fused pass: v -> regs, q -> Q[4][68] over B (src dead) ----
        float vv[2][8][2];
        {
            float bva = sm[B_BQKV+128+chA], bvb = sm[B_BQKV+128+chB];
            float bqa = sm[B_BQKV+chA],     bqb = sm[B_BQKV+chB];
            u64 v2[2][2][4], q2[2][2][2];
#pragma unroll
            for (int ee=0; ee<2; ee++) {
#pragma unroll
                for (int q=0;q<4;q++) {
                    v2[ee][0][q]=pk2(bva,bva); v2[ee][1][q]=pk2(bvb,bvb);
                }
                q2[ee][0][0]=q2[ee][0][1]=pk2(bqa,bqa);
                q2[ee][1][0]=q2[ee][1][1]=pk2(bqb,bqb);
            }
#pragma unroll 2
            for (int c = 0; c < 64; c++) {
                float2 wv = *(const float2*)(WqT + c*192 + 128 + wl2);
                float2 wq = *(const float2*)(WqT + c*192 + wl2);
                u64 wv0=pk2(wv.x,wv.x), wv1=pk2(wv.y,wv.y);
                u64 wq0=pk2(wq.x,wq.x), wq1=pk2(wq.y,wq.y);
#pragma unroll
                for (int ee=0; ee<2; ee++) {
                    ulonglong2 xlo = *(const ulonglong2*)(scr + ee*EFE + c*4);
                    ulonglong2 xhi = *(const ulonglong2*)(scr + ee*EFE + 256 + c*4);
                    fma2(v2[ee][0][0],xlo.x,wv0); fma2(v2[ee][0][1],xlo.y,wv0);
                    fma2(v2[ee][0][2],xhi.x,wv0); fma2(v2[ee][0][3],xhi.y,wv0);
                    fma2(v2[ee][1][0],xlo.x,wv1); fma2(v2[ee][1][1],xlo.y,wv1);
                    fma2(v2[ee][1][2],xhi.x,wv1); fma2(v2[ee][1][3],xhi.y,wv1);
                    fma2(q2[ee][0][0],xlo.x,wq0); fma2(q2[ee][0][1],xlo.y,wq0);
                    fma2(q2[ee][1][0],xlo.x,wq1); fma2(q2[ee][1][1],xlo.y,wq1);
                }
            }
            __syncwarp();   // src reads in b_proj done (already synced); Q overwrites B
#pragma unroll
            for (int ee=0; ee<2; ee++) {
                float* Qe = scr + ee*EFE + 512;
#pragma unroll
                for (int tp=0; tp<2; tp++) {
                    float a,b;
                    upk2(q2[ee][0][tp],a,b);
                    Qe[(2*tp)*68+chA]=a; Qe[(2*tp+1)*68+chA]=b;
                    upk2(q2[ee][1][tp],a,b);
                    Qe[(2*tp)*68+chB]=a; Qe[(2*tp+1)*68+chB]=b;
                }
#pragma unroll
                for (int tp=0; tp<4; tp++) {
                    upk2(v2[ee][0][tp], vv[ee][2*tp][0], vv[ee][2*tp+1][0]);
                    upk2(v2[ee][1][tp], vv[ee][2*tp][1], vv[ee][2*tp+1][1]);
                }
            }
        }
        __syncwarp();

        // ---- K pass: k -> A overlay [8][64] ----
        {
            float bka = sm[B_BQKV+64+chA], bkb = sm[B_BQKV+64+chB];
            u64 k2[2][2][4];
#pragma unroll
            for (int ee=0; ee<2; ee++)
#pragma unroll
                for (int q=0;q<4;q++) {
                    k2[ee][0][q]=pk2(bka,bka); k2[ee][1][q]=pk2(bkb,bkb);
                }
#pragma unroll 2
            for (int c = 0; c < 64; c++) {
                float2 wk = *(const float2*)(WqT + c*192 + 64 + wl2);
                u64 wk0=pk2(wk.x,wk.x), wk1=pk2(wk.y,wk.y);
#pragma unroll
                for (int ee=0; ee<2; ee++) {
                    ulonglong2 xlo = *(const ulonglong2*)(scr + ee*EFE + c*4);
                    ulonglong2 xhi = *(const ulonglong2*)(scr + ee*EFE + 256 + c*4);
                    fma2(k2[ee][0][0],xlo.x,wk0); fma2(k2[ee][0][1],xlo.y,wk0);
                    fma2(k2[ee][0][2],xhi.x,wk0); fma2(k2[ee][0][3],xhi.y,wk0);
                    fma2(k2[ee][1][0],xlo.x,wk1); fma2(k2[ee][1][1],xlo.y,wk1);
                    fma2(k2[ee][1][2],xhi.x,wk1); fma2(k2[ee][1][3],xhi.y,wk1);
                }
            }
            __syncwarp();   // all xC reads done before K overwrites A
#pragma unroll
            for (int ee=0; ee<2; ee++) {
                float* Ka = scr + ee*EFE;
#pragma unroll
                for (int tp=0; tp<4; tp++) {
                    float a,b;
                    upk2(k2[ee][0][tp],a,b);
                    Ka[(2*tp)*64+chA]=a; Ka[(2*tp+1)*64+chA]=b;
                    upk2(k2[ee][1][tp],a,b);
                    Ka[(2*tp)*64+chB]=a; Ka[(2*tp+1)*64+chB]=b;
                }
            }
        }
        __syncwarp();

        // ---- scores + softmax: lane = aee*16 + ah*4 + as ----
        float sc[8];
        {
            const int aee = lane>>4, ah = (lane>>2)&3, as = lane&3;
            const float* qr = scr + aee*EFE + 512 + as*68 + ah*16;
            float qv[16];
            *(float4*)(qv)    = *(const float4*)(qr);
            *(float4*)(qv+4)  = *(const float4*)(qr+4);
            *(float4*)(qv+8)  = *(const float4*)(qr+8);
            *(float4*)(qv+12) = *(const float4*)(qr+12);
            const float* Ka = scr + aee*EFE;
            float mx = -1e30f;
#pragma unroll
            for (int t = 0; t < 8; t++) {
                const float* kr = Ka + t*64 + ah*16;
                float kv[16];
                *(float4*)(kv)    = *(const float4*)(kr);
                *(float4*)(kv+4)  = *(const float4*)(kr+4);
                *(float4*)(kv+8)  = *(const float4*)(kr+8);
                *(float4*)(kv+12) = *(const float4*)(kr+12);
                float d = 0.f;
#pragma unroll
                for (int dd = 0; dd < 16; dd++) d += qv[dd]*kv[dd];
                d *= 0.25f;
                sc[t] = d; mx = fmaxf(mx, d);
            }
            float sum = 0.f;
#pragma unroll
            for (int t = 0; t < 8; t++) { sc[t] = __expf(sc[t]-mx); sum += sc[t]; }
            float inv = 1.0f/sum;
#pragma unroll
            for (int t = 0; t < 8; t++) sc[t] *= inv;
        }
        __syncwarp();   // all K/q reads done before o overlays A

        // ---- o-accum via shfl p-broadcast; v in regs ----
        {
            u64 o2[2][2][2];
#pragma unroll
            for (int ee=0; ee<2; ee++)
#pragma unroll
                for (int j=0;j<2;j++) { o2[ee][j][0]=0ull; o2[ee][j][1]=0ull; }
#pragma unroll
            for (int t = 0; t < 8; t++) {
                float pA[2][4], pB[2][4];
#pragma unroll
                for (int ee2=0; ee2<2; ee2++)
#pragma unroll
                    for (int s2=0; s2<4; s2++) {
                        pA[ee2][s2] = __shfl_sync(~0u, sc[t], ee2*16 + hLo*4 + s2);
                        pB[ee2][s2] = __shfl_sync(~0u, sc[t], ee2*16 + (hLo+2)*4 + s2);
                    }
#pragma unroll
                for (int ee2=0; ee2<2; ee2++) {
                    u64 ppA0 = pk2(pA[ee2][0], pA[ee2][1]);
                    u64 ppA1 = pk2(pA[ee2][2], pA[ee2][3]);
                    u64 ppB0 = pk2(pB[ee2][0], pB[ee2][1]);
                    u64 ppB1 = pk2(pB[ee2][2], pB[ee2][3]);
                    u64 vdA = pk2(vv[ee2][t][0], vv[ee2][t][0]);
                    u64 vdB = pk2(vv[ee2][t][1], vv[ee2][t][1]);
                    fma2(o2[ee2][0][0], ppA0, vdA); fma2(o2[ee2][0][1], ppA1, vdA);
                    fma2(o2[ee2][1][0], ppB0, vdB); fma2(o2[ee2][1][1], ppB1, vdB);
                }
            }
#pragma unroll
            for (int ee=0; ee<2; ee++) {
                float* Ae = scr + ee*EFE;
                float a0,a1,a2,a3;
                upk2(o2[ee][0][0],a0,a1); upk2(o2[ee][0][1],a2,a3);
                *(float4*)(Ae + chA*4) = make_float4(a0,a1,a2,a3);
                upk2(o2[ee][1][0],a0,a1); upk2(o2[ee][1][1],a2,a3);
                *(float4*)(Ae + chB*4) = make_float4(a0,a1,a2,a3);
            }
        }
        __syncwarp();

        // ---- Wo + residual + LN1 -> regs + x'[64][4]@A[256:512) ----
        {
            float b0f = sm[B_BO+chA], b1f = sm[B_BO+chB];
            u64 acc[2][2][2];
#pragma unroll
            for (int ee=0; ee<2; ee++) {
                acc[ee][0][0]=acc[ee][0][1]=pk2(b0f,b0f);
                acc[ee][1][0]=acc[ee][1][1]=pk2(b1f,b1f);
            }
            const float* o0p = scr; const float* o1p = scr+EFE;
#pragma unroll 4
            for (int c = 0; c < 64; c++) {
                float2 wp = *(const float2*)(WoT + c*64 + wl2);
                u64 w00=pk2(wp.x,wp.x), w11=pk2(wp.y,wp.y);
                ulonglong2 x0 = *(const ulonglong2*)(o0p + c*4);
                ulonglong2 x1 = *(const ulonglong2*)(o1p + c*4);
                fma2(acc[0][0][0],x0.x,w00); fma2(acc[0][0][1],x0.y,w00);
                fma2(acc[0][1][0],x0.x,w11); fma2(acc[0][1][1],x0.y,w11);
                fma2(acc[1][0][0],x1.x,w00); fma2(acc[1][0][1],x1.y,w00);
                fma2(acc[1][1][0],x1.x,w11); fma2(acc[1][1][1],x1.y,w11);
            }
            float ga = sm[B_G1+chA], gb = sm[B_G1+chB];
            float ba = sm[B_BE1+chA], bb2 = sm[B_BE1+chB];
#pragma unroll
            for (int ee=0; ee<2; ee++) {
                float a[2][4];
                upk2(acc[ee][0][0],a[0][0],a[0][1]); upk2(acc[ee][0][1],a[0][2],a[0][3]);
                upk2(acc[ee][1][0],a[1][0],a[1][1]); upk2(acc[ee][1][1],a[1][2],a[1][3]);
#pragma unroll
                for (int s = 0; s < 4; s++) {
                    float v0 = a[0][s] + xr[ee][0][s];
                    float v1 = a[1][s] + xr[ee][1][s];
                    lnpair(v0, v1, ga, gb, ba, bb2);
                    xln[ee][0][s]=v0; xln[ee][1][s]=v1;
                }
                float* Xe = scr + ee*EFE + 256;
                *(float4*)(Xe + chA*4) = make_float4(xln[ee][0][0],xln[ee][0][1],
                                                    xln[ee][0][2],xln[ee][0][3]);
                *(float4*)(Xe + chB*4) = make_float4(xln[ee][1][0],xln[ee][1][1],
                                                    xln[ee][1][2],xln[ee][1][3]);
            }
        }
        __syncwarp();

        // ---- FF1: relu -> hidden[64][4]@B ----
        {
            float b0f = sm[B_BF1+chA], b1f = sm[B_BF1+chB];
            u64 acc[2][2][2];
#pragma unroll
            for (int ee=0; ee<2; ee++) {
                acc[ee][0][0]=acc[ee][0][1]=pk2(b0f,b0f);
                acc[ee][1][0]=acc[ee][1][1]=pk2(b1f,b1f);
            }
            const float* x0p = scr+256; const float* x1p = scr+EFE+256;
#pragma unroll 4
            for (int c = 0; c < 64; c++) {
                float2 wp = *(const float2*)(W1T + c*64 + wl2);
                u64 w00=pk2(wp.x,wp.x), w11=pk2(wp.y,wp.y);
                ulonglong2 x0 = *(const ulonglong2*)(x0p + c*4);
                ulonglong2 x1 = *(const ulonglong2*)(x1p + c*4);
                fma2(acc[0][0][0],x0.x,w00); fma2(acc[0][0][1],x0.y,w00);
                fma2(acc[0][1][0],x0.x,w11); fma2(acc[0][1][1],x0.y,w11);
                fma2(acc[1][0][0],x1.x,w00); fma2(acc[1][0][1],x1.y,w00);
                fma2(acc[1][1][0],x1.x,w11); fma2(acc[1][1][1],x1.y,w11);
            }
#pragma unroll
            for (int ee=0; ee<2; ee++) {
                float* He = scr + ee*EFE + 512;
                float a0,a1,a2,a3;
                upk2(acc[ee][0][0],a0,a1); upk2(acc[ee][0][1],a2,a3);
                *(float4*)(He + chA*4) = make_float4(fmaxf(a0,0.f),fmaxf(a1,0.f),
                                                    fmaxf(a2,0.f),fmaxf(a3,0.f));
                upk2(acc[ee][1][0],a0,a1); upk2(acc[ee][1][1],a2,a3);
                *(float4*)(He + chB*4) = make_float4(fmaxf(a0,0.f),fmaxf(a1,0.f),
                                                    fmaxf(a2,0.f),fmaxf(a3,0.f));
            }
        }
        __syncwarp();

        // ---- FF2 + residual + LN2 + scatter (paired accum layout) ----
        {
            float b0f = sm[B_BF2+chA], b1f = sm[B_BF2+chB];
            u64 acc[2][2][2];
#pragma unroll
            for (int ee=0; ee<2; ee++) {
                acc[ee][0][0]=acc[ee][0][1]=pk2(b0f,b0f);
                acc[ee][1][0]=acc[ee][1][1]=pk2(b1f,b1f);
            }
            const float* h0p = scr+512; const float* h1p = scr+EFE+512;
#pragma unroll 4
            for (int f = 0; f < 64; f++) {
                float2 wp = *(const float2*)(W2T + f*64 + wl2);
                u64 w00=pk2(wp.x,wp.x), w11=pk2(wp.y,wp.y);
                ulonglong2 x0 = *(const ulonglong2*)(h0p + f*4);
                ulonglong2 x1 = *(const ulonglong2*)(h1p + f*4);
                fma2(acc[0][0][0],x0.x,w00); fma2(acc[0][0][1],x0.y,w00);
                fma2(acc[0][1][0],x0.x,w11); fma2(acc[0][1][1],x0.y,w11);
                fma2(acc[1][0][0],x1.x,w00); fma2(acc[1][0][1],x1.y,w00);
                fma2(acc[1][1][0],x1.x,w11); fma2(acc[1][1][1],x1.y,w11);
            }
            float ga = sm[B_G2+chA], gb = sm[B_G2+chB];
            float ba = sm[B_BE2+chA], bb2 = sm[B_BE2+chB];
#pragma unroll
            for (int ee=0; ee<2; ee++) {
                float a[2][4];
                upk2(acc[ee][0][0],a[0][0],a[0][1]); upk2(acc[ee][0][1],a[0][2],a[0][3]);
                upk2(acc[ee][1][0],a[1][0],a[1][1]); upk2(acc[ee][1][1],a[1][2],a[1][3]);
                float* outp = accum + (size_t)(ee?di1:di0)*256;
#pragma unroll
                for (int s = 0; s < 4; s++) {
                    float v0 = a[0][s] + xln[ee][0][s];
                    float v1 = a[1][s] + xln[ee][1][s];
                    lnpair(v0, v1, ga, gb, ba, bb2);
                    red2(outp + s*64 + lane*2, v0, v1);
                }
            }
            if (lane == 0) { atomicAdd(cnt+di0, 1.0f); atomicAdd(cnt+di1, 1.0f); }
        }
        __syncwarp();
    }
}

__global__ void __launch_bounds__(256) final_kernel(
    const float* __restrict__ Wout, const float* __restrict__ bout,
    float* __restrict__ out)
{
    __shared__ float WoT[2048];
    __shared__ float xs[8][64];
    const int tid = threadIdx.x;
    for (int i = tid; i < 2048; i += 256) {
        int o = i>>6, c = i&63;
        WoT[c*32+o] = Wout[i];
    }
    __syncthreads();
    const int wrp = tid>>5, lane = tid&31;
    const int n = blockIdx.x*8 + wrp;
    if (n >= NA_) return;
    float c0 = g_cnt[0][n], c1 = g_cnt[1][n];
    float i0 = (c0>0.f) ? 0.5f/c0 : 0.f;
    float i1 = (c1>0.f) ? 0.5f/c1 : 0.f;
    const float* a0p = &g_accum[0][n][0];
    const float* a1p = &g_accum[1][n][0];
    // paired layout: channel lane at t*64+lane*2, channel lane+32 at +1
    float s0 = 0.f, s1 = 0.f;
#pragma unroll
    for (int t = 0; t < 4; t++) {
        s0 += a0p[t*64+lane*2]  *i0 + a1p[t*64+lane*2]  *i1;
        s1 += a0p[t*64+lane*2+1]*i0 + a1p[t*64+lane*2+1]*i1;
    }
    xs[wrp][lane] = s0; xs[wrp][lane+32] = s1;
    __syncwarp();
    float lg = 4.0f*bout[lane];
#pragma unroll
    for (int c = 0; c < 64; c++) lg += xs[wrp][c]*WoT[c*32+lane];
    float m = lg;
#pragma unroll
    for (int o = 16; o; o >>= 1) m = fmaxf(m, __shfl_xor_sync(~0u, m, o));
    float ev = __expf(lg - m);
    float sum = ev;
#pragma unroll
    for (int o = 16; o; o >>= 1) sum += __shfl_xor_sync(~0u, sum, o);
    out[(size_t)n*32 + lane] = ev/sum;
}

extern "C" void kernel_launch(void* const* d_in, const int* in_sizes, int n_in,
                              void* d_out, int out_size) {
    const float* xA   = (const float*)d_in[0];
    const float* xB   = (const float*)d_in[1];
    const int*   e_ba = (const int*)d_in[2];
    const int*   e_aa = (const int*)d_in[3];
    const float* Wb   = (const float*)d_in[4];
    const float* bb   = (const float*)d_in[5];
    const float* Wqkv = (const float*)d_in[6];
    const float* bqkv = (const float*)d_in[7];
    const float* Wo   = (const float*)d_in[8];
    const float* bo   = (const float*)d_in[9];
    const float* g1   = (const float*)d_in[10];
    const float* be1  = (const float*)d_in[11];
    const float* W1   = (const float*)d_in[12];
    const float* bf1  = (const float*)d_in[13];
    const float* W2   = (const float*)d_in[14];
    const float* bf2  = (const float*)d_in[15];
    const float* g2   = (const float*)d_in[16];
    const float* be2  = (const float*)d_in[17];
    const float* Wout = (const float*)d_in[18];
    const float* bout = (const float*)d_in[19];

    cudaFuncSetAttribute(edge_kernel,
                         cudaFuncAttributeMaxDynamicSharedMemorySize, SMEM_BYTES);
    // g_accum zero at module load; zero_kernel at END primes next call.
    edge_kernel<<<dim3(148,2), 384, SMEM_BYTES>>>(
        xA, xB, e_ba, e_aa, Wb, bb, Wqkv, bqkv, Wo, bo,
        g1, be1, W1, bf1, W2, bf2, g2, be2);
    final_kernel<<<(NA_+7)/8, 256>>>(Wout, bout, (float*)d_out);
    zero_kernel<<<1024, 256>>>();
}

// round 15
// speedup vs baseline: 1.8889x; 1.4524x over previous
#include <cuda_runtime.h>
typedef unsigned long long u64;
#define NA_ 40000
#define NE_ 150000

// ================= device tables =================
__device__ __align__(16) float g_qkv [2][NA_][768];  // dst: q0-3|k0-3|v0-3 rows of 64
__device__ __align__(16) float g_kv47[2][NA_][512];  // src: k4-7|v4-7 rows of 64
__device__ __align__(16) float g_accum[2][NA_][256];
__device__ __align__(16) float g_cnt[2][NA_];

__global__ void zero_kernel() {
    float4* a = (float4*)&g_accum[0][0][0];
    const int n4 = 2*NA_*64;
    for (int i = blockIdx.x*blockDim.x+threadIdx.x; i < n4; i += gridDim.x*blockDim.x)
        a[i] = make_float4(0.f,0.f,0.f,0.f);
    float4* c = (float4*)&g_cnt[0][0];
    for (int i = blockIdx.x*blockDim.x+threadIdx.x; i < 2*NA_/4; i += gridDim.x*blockDim.x)
        c[i] = make_float4(0.f,0.f,0.f,0.f);
}

__device__ __forceinline__ u64 pk2(float a, float b) {
    u64 r; asm("mov.b64 %0,{%1,%2};" : "=l"(r) : "f"(a), "f"(b)); return r;
}
__device__ __forceinline__ void upk2(u64 v, float& a, float& b) {
    asm("mov.b64 {%0,%1},%2;" : "=f"(a), "=f"(b) : "l"(v));
}
__device__ __forceinline__ void fma2(u64& d, u64 a, u64 b) {
    asm("fma.rn.f32x2 %0,%1,%2,%0;" : "+l"(d) : "l"(a), "l"(b));
}
__device__ __forceinline__ void lnpair(float& v0, float& v1, float ga, float gb,
                                       float ba, float bb2) {
    float sum = v0+v1, sq = v0*v0+v1*v1;
#pragma unroll
    for (int o = 16; o; o >>= 1) {
        sum += __shfl_xor_sync(~0u, sum, o);
        sq  += __shfl_xor_sync(~0u, sq, o);
    }
    float m = sum*(1.f/64.f);
    float rs = rsqrtf(sq*(1.f/64.f)-m*m+1e-5f);
    v0 = (v0-m)*rs*ga+ba; v1 = (v1-m)*rs*gb+bb2;
}
__device__ __forceinline__ void red2(float* p, float a, float b) {
    asm volatile("red.global.add.v2.f32 [%0],{%1,%2};" :: "l"(p), "f"(a), "f"(b) : "memory");
}

// ================= precompute: dst q,k,v tokens 0-3 =================
#define PD_WQ 0
#define PD_BQ 12288
#define PD_SCR 12480
#define PD_SMEM ((PD_SCR + 8*256)*4)   // 58112 B
__global__ void __launch_bounds__(256,1) pre_dst_kernel(
    const float* __restrict__ xA,
    const float* __restrict__ Wqkv, const float* __restrict__ bqkv)
{
    extern __shared__ float sm[];
    const int k = blockIdx.y, tid = threadIdx.x;
    {
        const float* sq = Wqkv + k*12288;
        for (int i = tid; i < 12288; i += 256) {
            int o = i>>6, c = i&63;
            int blk = o>>6, oo = o&63;
            int po = ((oo&31)<<1) | (oo>>5);
            sm[PD_WQ + c*192 + blk*64 + po] = sq[i];
        }
        if (tid < 192) sm[PD_BQ+tid] = bqkv[k*192+tid];
    }
    __syncthreads();
    const int lane = tid & 31, wrp = tid >> 5;
    const int chA = lane, chB = lane + 32, wl2 = 2*lane;
    float* xc = sm + PD_SCR + wrp*256;
    const float* WqT = sm + PD_WQ;

    for (int n = blockIdx.x*8 + wrp; n < NA_; n += 148*8) {
        const float* xd = xA + (size_t)n*256;
        float dA[4], dB[4];
#pragma unroll
        for (int s = 0; s < 4; s++) { dA[s]=xd[s*64+chA]; dB[s]=xd[s*64+chB]; }
        *(float4*)(xc + chA*4) = make_float4(dA[0],dA[1],dA[2],dA[3]);
        *(float4*)(xc + chB*4) = make_float4(dB[0],dB[1],dB[2],dB[3]);
        __syncwarp();

        float bqa=sm[PD_BQ+chA],     bqb=sm[PD_BQ+chB];
        float bka=sm[PD_BQ+64+chA],  bkb=sm[PD_BQ+64+chB];
        float bva=sm[PD_BQ+128+chA], bvb=sm[PD_BQ+128+chB];
        u64 q2[2][2], k2[2][2], v2[2][2];
        q2[0][0]=q2[0][1]=pk2(bqa,bqa); q2[1][0]=q2[1][1]=pk2(bqb,bqb);
        k2[0][0]=k2[0][1]=pk2(bka,bka); k2[1][0]=k2[1][1]=pk2(bkb,bkb);
        v2[0][0]=v2[0][1]=pk2(bva,bva); v2[1][0]=v2[1][1]=pk2(bvb,bvb);
#pragma unroll 4
        for (int c = 0; c < 64; c++) {
            float2 wq = *(const float2*)(WqT + c*192 + wl2);
            float2 wk = *(const float2*)(WqT + c*192 + 64 + wl2);
            float2 wv = *(const float2*)(WqT + c*192 + 128 + wl2);
            ulonglong2 x = *(const ulonglong2*)(xc + c*4);
            u64 a0=pk2(wq.x,wq.x), a1=pk2(wq.y,wq.y);
            fma2(q2[0][0],x.x,a0); fma2(q2[0][1],x.y,a0);
            fma2(q2[1][0],x.x,a1); fma2(q2[1][1],x.y,a1);
            a0=pk2(wk.x,wk.x); a1=pk2(wk.y,wk.y);
            fma2(k2[0][0],x.x,a0); fma2(k2[0][1],x.y,a0);
            fma2(k2[1][0],x.x,a1); fma2(k2[1][1],x.y,a1);
            a0=pk2(wv.x,wv.x); a1=pk2(wv.y,wv.y);
            fma2(v2[0][0],x.x,a0); fma2(v2[0][1],x.y,a0);
            fma2(v2[1][0],x.x,a1); fma2(v2[1][1],x.y,a1);
        }
        float* op = &g_qkv[k][n][0];
#pragma unroll
        for (int j = 0; j < 2; j++) {
            int ch = j ? chB : chA;
            float a,b;
#pragma unroll
            for (int tp = 0; tp < 2; tp++) {
                upk2(q2[j][tp],a,b); op[(2*tp)*64+ch]=a;     op[(2*tp+1)*64+ch]=b;
                upk2(k2[j][tp],a,b); op[(4+2*tp)*64+ch]=a;   op[(5+2*tp)*64+ch]=b;
                upk2(v2[j][tp],a,b); op[(8+2*tp)*64+ch]=a;   op[(9+2*tp)*64+ch]=b;
            }
        }
        __syncwarp();
    }
}

// ================= precompute: src b_proj -> k,v tokens 4-7 =================
#define PS_WB 0
#define PS_WQ 4096
#define PS_BB 16384
#define PS_BQ 16448
#define PS_SCR 16640
#define PS_SMEM ((PS_SCR + 8*512)*4)   // 82944 B
__global__ void __launch_bounds__(256,1) pre_src_kernel(
    const float* __restrict__ xA, const float* __restrict__ xB,
    const float* __restrict__ Wb, const float* __restrict__ bb,
    const float* __restrict__ Wqkv, const float* __restrict__ bqkv)
{
    extern __shared__ float sm[];
    const int k = blockIdx.y, tid = threadIdx.x;
    {
        const float* s1 = Wb + k*4096;
        for (int i = tid; i < 4096; i += 256) {
            int o = i>>6, c = i&63;
            int po = ((o&31)<<1) | (o>>5);
            sm[PS_WB + c*64 + po] = s1[i];
        }
        const float* sq = Wqkv + k*12288;
        for (int i = tid; i < 12288; i += 256) {
            int o = i>>6, c = i&63;
            int blk = o>>6, oo = o&63;
            int po = ((oo&31)<<1) | (oo>>5);
            sm[PS_WQ + c*192 + blk*64 + po] = sq[i];
        }
        if (tid < 64)  sm[PS_BB+tid] = bb[k*64+tid];
        if (tid < 192) sm[PS_BQ+tid] = bqkv[k*192+tid];
    }
    __syncthreads();
    const int lane = tid & 31, wrp = tid >> 5;
    const int chA = lane, chB = lane + 32, wl2 = 2*lane;
    float* xs = sm + PS_SCR + wrp*512;
    float* xb = xs + 256;
    const float* WbT = sm + PS_WB;
    const float* WqT = sm + PS_WQ;
    const float* xsrc = (k==0) ? xB : xA;

    for (int n = blockIdx.x*8 + wrp; n < NA_; n += 148*8) {
        const float* xp = xsrc + (size_t)n*256;
        float sA[4], sB[4];
#pragma unroll
        for (int s = 0; s < 4; s++) { sA[s]=xp[s*64+chA]; sB[s]=xp[s*64+chB]; }
        *(float4*)(xs + chA*4) = make_float4(sA[0],sA[1],sA[2],sA[3]);
        *(float4*)(xs + chB*4) = make_float4(sB[0],sB[1],sB[2],sB[3]);
        __syncwarp();

        // b_proj
        {
            float b0f = sm[PS_BB+chA], b1f = sm[PS_BB+chB];
            u64 acc[2][2];
            acc[0][0]=acc[0][1]=pk2(b0f,b0f);
            acc[1][0]=acc[1][1]=pk2(b1f,b1f);
#pragma unroll 4
            for (int c = 0; c < 64; c++) {
                float2 wp = *(const float2*)(WbT + c*64 + wl2);
                u64 w00=pk2(wp.x,wp.x), w11=pk2(wp.y,wp.y);
                ulonglong2 x = *(const ulonglong2*)(xs + c*4);
                fma2(acc[0][0],x.x,w00); fma2(acc[0][1],x.y,w00);
                fma2(acc[1][0],x.x,w11); fma2(acc[1][1],x.y,w11);
            }
            float a0,a1,a2,a3;
            upk2(acc[0][0],a0,a1); upk2(acc[0][1],a2,a3);
            *(float4*)(xb + chA*4) = make_float4(a0,a1,a2,a3);
            upk2(acc[1][0],a0,a1); upk2(acc[1][1],a2,a3);
            *(float4*)(xb + chB*4) = make_float4(a0,a1,a2,a3);
        }
        __syncwarp();

        // k,v over xb
        {
            float bka=sm[PS_BQ+64+chA],  bkb=sm[PS_BQ+64+chB];
            float bva=sm[PS_BQ+128+chA], bvb=sm[PS_BQ+128+chB];
            u64 k2[2][2], v2[2][2];
            k2[0][0]=k2[0][1]=pk2(bka,bka); k2[1][0]=k2[1][1]=pk2(bkb,bkb);
            v2[0][0]=v2[0][1]=pk2(bva,bva); v2[1][0]=v2[1][1]=pk2(bvb,bvb);
#pragma unroll 4
            for (int c = 0; c < 64; c++) {
                float2 wk = *(const float2*)(WqT + c*192 + 64 + wl2);
                float2 wv = *(const float2*)(WqT + c*192 + 128 + wl2);
                ulonglong2 x = *(const ulonglong2*)(xb + c*4);
                u64 a0=pk2(wk.x,wk.x), a1=pk2(wk.y,wk.y);
                fma2(k2[0][0],x.x,a0); fma2(k2[0][1],x.y,a0);
                fma2(k2[1][0],x.x,a1); fma2(k2[1][1],x.y,a1);
                a0=pk2(wv.x,wv.x); a1=pk2(wv.y,wv.y);
                fma2(v2[0][0],x.x,a0); fma2(v2[0][1],x.y,a0);
                fma2(v2[1][0],x.x,a1); fma2(v2[1][1],x.y,a1);
            }
            float* op = &g_kv47[k][n][0];
#pragma unroll
            for (int j = 0; j < 2; j++) {
                int ch = j ? chB : chA;
                float a,b;
#pragma unroll
                for (int tp = 0; tp < 2; tp++) {
                    upk2(k2[j][tp],a,b); op[(2*tp)*64+ch]=a;   op[(2*tp+1)*64+ch]=b;
                    upk2(v2[j][tp],a,b); op[(4+2*tp)*64+ch]=a; op[(5+2*tp)*64+ch]=b;
                }
            }
        }
        __syncwarp();
    }
}

// ================= edge kernel =================
#define W_WO2 0
#define W_W12 4096
#define W_W22 8192
#define B2_BO 12288
#define B2_G1 12352
#define B2_BE1 12416
#define B2_BF1 12480
#define B2_BF2 12544
#define B2_G2 12608
#define B2_BE2 12672
#define SCR2 12736
// per-edge EFE=784: A[0:512)=K[8][64] -> o[64][4]@0 + x'[64][4]@256 ; B[512:784)=Q[4][68] -> hidden[64][4]
#define EFE 784
#define WFE (2*EFE)
#define NW 14
#define SMEM_E ((SCR2 + NW*WFE)*4)   // 138752 B

__global__ void __launch_bounds__(32*NW,1) edge_kernel(
    const float* __restrict__ xA,
    const int* __restrict__ e_ba, const int* __restrict__ e_aa,
    const float* __restrict__ Wo, const float* __restrict__ bo,
    const float* __restrict__ g1, const float* __restrict__ be1,
    const float* __restrict__ W1, const float* __restrict__ bf1,
    const float* __restrict__ W2, const float* __restrict__ bf2,
    const float* __restrict__ g2, const float* __restrict__ be2)
{
    extern __shared__ float sm[];
    const int k = blockIdx.y, tid = threadIdx.x;
    {
        const float* s2 = Wo + k*4096;
        const float* s3 = W1 + k*4096;
        const float* s4 = W2 + k*4096;
        for (int i = tid; i < 4096; i += 32*NW) {
            int o = i>>6, c = i&63;
            int po = ((o&31)<<1) | (o>>5);
            sm[W_WO2 + c*64 + po] = s2[i];
            sm[W_W12 + c*64 + po] = s3[i];
            sm[W_W22 + c*64 + po] = s4[i];
        }
        if (tid < 64) {
            sm[B2_BO+tid]=bo[k*64+tid];
            sm[B2_G1+tid]=g1[k*64+tid];   sm[B2_BE1+tid]=be1[k*64+tid];
            sm[B2_BF1+tid]=bf1[k*64+tid]; sm[B2_BF2+tid]=bf2[k*64+tid];
            sm[B2_G2+tid]=g2[k*64+tid];   sm[B2_BE2+tid]=be2[k*64+tid];
        }
    }
    __syncthreads();

    const int* Es = (k==0) ? e_ba : e_aa;
    const int* Ed = Es + NE_;
    const float* gq = &g_qkv[k][0][0];
    const float* gs = &g_kv47[k][0][0];
    float* accum = &g_accum[k][0][0];
    float* cnt = &g_cnt[k][0];

    const int lane = tid & 31, wrp = tid >> 5;
    const int chA = lane, chB = lane + 32;
    const int hLo = lane >> 4;
    const int wl2 = 2*lane;
    float* scr = sm + SCR2 + wrp*WFE;
    const float* WoT = sm+W_WO2;  const float* W1T = sm+W_W12;
    const float* W2T = sm+W_W22;

    for (int p = blockIdx.x*NW + wrp; p < NE_/2; p += 148*NW) {
        const int e0 = 2*p, e1 = 2*p+1;
        const int si0 = Es[e0], si1 = Es[e1], di0 = Ed[e0], di1 = Ed[e1];
        float xr[2][2][4], xln[2][2][4], vv[2][8][2];

        // ---- gather staging: qkv tables -> smem/regs ----
#pragma unroll
        for (int ee = 0; ee < 2; ee++) {
            const int di = ee ? di1 : di0, si = ee ? si1 : si0;
            const float* qp = gq + (size_t)di*768;
            const float* sp = gs + (size_t)si*512;
            const float* xd = xA + (size_t)di*256;
            float* Ka = scr + ee*EFE;
            float* Qe = Ka + 512;
#pragma unroll
            for (int t = 0; t < 4; t++) {
                Qe[t*68+chA]     = qp[t*64+chA];     Qe[t*68+chB]     = qp[t*64+chB];
                Ka[t*64+chA]     = qp[(4+t)*64+chA]; Ka[t*64+chB]     = qp[(4+t)*64+chB];
                vv[ee][t][0]     = qp[(8+t)*64+chA]; vv[ee][t][1]     = qp[(8+t)*64+chB];
                Ka[(4+t)*64+chA] = sp[t*64+chA];     Ka[(4+t)*64+chB] = sp[t*64+chB];
                vv[ee][4+t][0]   = sp[(4+t)*64+chA]; vv[ee][4+t][1]   = sp[(4+t)*64+chB];
                xr[ee][0][t] = xd[t*64+chA];
                xr[ee][1][t] = xd[t*64+chB];
            }
        }
        __syncwarp();

        // ---- scores + softmax: lane = aee*16 + ah*4 + as ----
        float sc[8];
        {
            const int aee = lane>>4, ah = (lane>>2)&3, as = lane&3;
            const float* qr = scr + aee*EFE + 512 + as*68 + ah*16;
            float qv[16];
            *(float4*)(qv)    = *(const float4*)(qr);
            *(float4*)(qv+4)  = *(const float4*)(qr+4);
            *(float4*)(qv+8)  = *(const float4*)(qr+8);
            *(float4*)(qv+12) = *(const float4*)(qr+12);
            const float* Ka = scr + aee*EFE;
            float mx = -1e30f;
#pragma unroll
            for (int t = 0; t < 8; t++) {
                const float* kr = Ka + t*64 + ah*16;
                float kv[16];
                *(float4*)(kv)    = *(const float4*)(kr);
                *(float4*)(kv+4)  = *(const float4*)(kr+4);
                *(float4*)(kv+8)  = *(const float4*)(kr+8);
                *(float4*)(kv+12) = *(const float4*)(kr+12);
                float d = 0.f;
#pragma unroll
                for (int dd = 0; dd < 16; dd++) d += qv[dd]*kv[dd];
                d *= 0.25f;
                sc[t] = d; mx = fmaxf(mx, d);
            }
            float sum = 0.f;
#pragma unroll
            for (int t = 0; t < 8; t++) { sc[t] = __expf(sc[t]-mx); sum += sc[t]; }
            float inv = 1.0f/sum;
#pragma unroll
            for (int t = 0; t < 8; t++) sc[t] *= inv;
        }
        __syncwarp();   // all K/Q reads done before o overlays A

        // ---- o-accum via shfl p-broadcast; v in regs ----
        {
            u64 o2[2][2][2];
#pragma unroll
            for (int ee=0; ee<2; ee++)
#pragma unroll
                for (int j=0;j<2;j++) { o2[ee][j][0]=0ull; o2[ee][j][1]=0ull; }
#pragma unroll
            for (int t = 0; t < 8; t++) {
                float pA[2][4], pB[2][4];
#pragma unroll
                for (int ee2=0; ee2<2; ee2++)
#pragma unroll
                    for (int s2=0; s2<4; s2++) {
                        pA[ee2][s2] = __shfl_sync(~0u, sc[t], ee2*16 + hLo*4 + s2);
                        pB[ee2][s2] = __shfl_sync(~0u, sc[t], ee2*16 + (hLo+2)*4 + s2);
                    }
#pragma unroll
                for (int ee2=0; ee2<2; ee2++) {
                    u64 ppA0 = pk2(pA[ee2][0], pA[ee2][1]);
                    u64 ppA1 = pk2(pA[ee2][2], pA[ee2][3]);
                    u64 ppB0 = pk2(pB[ee2][0], pB[ee2][1]);
                    u64 ppB1 = pk2(pB[ee2][2], pB[ee2][3]);
                    u64 vdA = pk2(vv[ee2][t][0], vv[ee2][t][0]);
                    u64 vdB = pk2(vv[ee2][t][1], vv[ee2][t][1]);
                    fma2(o2[ee2][0][0], ppA0, vdA); fma2(o2[ee2][0][1], ppA1, vdA);
                    fma2(o2[ee2][1][0], ppB0, vdB); fma2(o2[ee2][1][1], ppB1, vdB);
                }
            }
#pragma unroll
            for (int ee=0; ee<2; ee++) {
                float* Ae = scr + ee*EFE;
                float a0,a1,a2,a3;
                upk2(o2[ee][0][0],a0,a1); upk2(o2[ee][0][1],a2,a3);
                *(float4*)(Ae + chA*4) = make_float4(a0,a1,a2,a3);
                upk2(o2[ee][1][0],a0,a1); upk2(o2[ee][1][1],a2,a3);
                *(float4*)(Ae + chB*4) = make_float4(a0,a1,a2,a3);
            }
        }
        __syncwarp();

        // ---- Wo + residual + LN1 -> regs + x'[64][4]@A[256:512) ----
        {
            float b0f = sm[B2_BO+chA], b1f = sm[B2_BO+chB];
            u64 acc[2][2][2];
#pragma unroll
            for (int ee=0; ee<2; ee++) {
                acc[ee][0][0]=acc[ee][0][1]=pk2(b0f,b0f);
                acc[ee][1][0]=acc[ee][1][1]=pk2(b1f,b1f);
            }
            const float* o0p = scr; const float* o1p = scr+EFE;
#pragma unroll 4
            for (int c = 0; c < 64; c++) {
                float2 wp = *(const float2*)(WoT + c*64 + wl2);
                u64 w00=pk2(wp.x,wp.x), w11=pk2(wp.y,wp.y);
                ulonglong2 x0 = *(const ulonglong2*)(o0p + c*4);
                ulonglong2 x1 = *(const ulonglong2*)(o1p + c*4);
                fma2(acc[0][0][0],x0.x,w00); fma2(acc[0][0][1],x0.y,w00);
                fma2(acc[0][1][0],x0.x,w11); fma2(acc[0][1][1],x0.y,w11);
                fma2(acc[1][0][0],x1.x,w00); fma2(acc[1][0][1],x1.y,w00);
                fma2(acc[1][1][0],x1.x,w11); fma2(acc[1][1][1],x1.y,w11);
            }
            float ga = sm[B2_G1+chA], gb = sm[B2_G1+chB];
            float ba = sm[B2_BE1+chA], bb2 = sm[B2_BE1+chB];
#pragma unroll
            for (int ee=0; ee<2; ee++) {
                float a[2][4];
                upk2(acc[ee][0][0],a[0][0],a[0][1]); upk2(acc[ee][0][1],a[0][2],a[0][3]);
                upk2(acc[ee][1][0],a[1][0],a[1][1]); upk2(acc[ee][1][1],a[1][2],a[1][3]);
#pragma unroll
                for (int s = 0; s < 4; s++) {
                    float v0 = a[0][s] + xr[ee][0][s];
                    float v1 = a[1][s] + xr[ee][1][s];
                    lnpair(v0, v1, ga, gb, ba, bb2);
                    xln[ee][0][s]=v0; xln[ee][1][s]=v1;
                }
                float* Xe = scr + ee*EFE + 256;
                *(float4*)(Xe + chA*4) = make_float4(xln[ee][0][0],xln[ee][0][1],
                                                    xln[ee][0][2],xln[ee][0][3]);
                *(float4*)(Xe + chB*4) = make_float4(xln[ee][1][0],xln[ee][1][1],
                                                    xln[ee][1][2],xln[ee][1][3]);
            }
        }
        __syncwarp();

        // ---- FF1: relu -> hidden[64][4]@B (overlays Q) ----
        {
            float b0f = sm[B2_BF1+chA], b1f = sm[B2_BF1+chB];
            u64 acc[2][2][2];
#pragma unroll
            for (int ee=0; ee<2; ee++) {
                acc[ee][0][0]=acc[ee][0][1]=pk2(b0f,b0f);
                acc[ee][1][0]=acc[ee][1][1]=pk2(b1f,b1f);
            }
            const float* x0p = scr+256; const float* x1p = scr+EFE+256;
#pragma unroll 4
            for (int c = 0; c < 64; c++) {
                float2 wp = *(const float2*)(W1T + c*64 + wl2);
                u64 w00=pk2(wp.x,wp.x), w11=pk2(wp.y,wp.y);
                ulonglong2 x0 = *(const ulonglong2*)(x0p + c*4);
                ulonglong2 x1 = *(const ulonglong2*)(x1p + c*4);
                fma2(acc[0][0][0],x0.x,w00); fma2(acc[0][0][1],x0.y,w00);
                fma2(acc[0][1][0],x0.x,w11); fma2(acc[0][1][1],x0.y,w11);
                fma2(acc[1][0][0],x1.x,w00); fma2(acc[1][0][1],x1.y,w00);
                fma2(acc[1][1][0],x1.x,w11); fma2(acc[1][1][1],x1.y,w11);
            }
#pragma unroll
            for (int ee=0; ee<2; ee++) {
                float* He = scr + ee*EFE + 512;
                float a0,a1,a2,a3;
                upk2(acc[ee][0][0],a0,a1); upk2(acc[ee][0][1],a2,a3);
                *(float4*)(He + chA*4) = make_float4(fmaxf(a0,0.f),fmaxf(a1,0.f),
                                                    fmaxf(a2,0.f),fmaxf(a3,0.f));
                upk2(acc[ee][1][0],a0,a1); upk2(acc[ee][1][1],a2,a3);
                *(float4*)(He + chB*4) = make_float4(fmaxf(a0,0.f),fmaxf(a1,0.f),
                                                    fmaxf(a2,0.f),fmaxf(a3,0.f));
            }
        }
        __syncwarp();

        // ---- FF2 + residual + LN2 + scatter (paired accum layout) ----
        {
            float b0f = sm[B2_BF2+chA], b1f = sm[B2_BF2+chB];
            u64 acc[2][2][2];
#pragma unroll
            for (int ee=0; ee<2; ee++) {
                acc[ee][0][0]=acc[ee][0][1]=pk2(b0f,b0f);
                acc[ee][1][0]=acc[ee][1][1]=pk2(b1f,b1f);
            }
            const float* h0p = scr+512; const float* h1p = scr+EFE+512;
#pragma unroll 4
            for (int f = 0; f < 64; f++) {
                float2 wp = *(const float2*)(W2T + f*64 + wl2);
                u64 w00=pk2(wp.x,wp.x), w11=pk2(wp.y,wp.y);
                ulonglong2 x0 = *(const ulonglong2*)(h0p + f*4);
                ulonglong2 x1 = *(const ulonglong2*)(h1p + f*4);
                fma2(acc[0][0][0],x0.x,w00); fma2(acc[0][0][1],x0.y,w00);
                fma2(acc[0][1][0],x0.x,w11); fma2(acc[0][1][1],x0.y,w11);
                fma2(acc[1][0][0],x1.x,w00); fma2(acc[1][0][1],x1.y,w00);
                fma2(acc[1][1][0],x1.x,w11); fma2(acc[1][1][1],x1.y,w11);
            }
            float ga = sm[B2_G2+chA], gb = sm[B2_G2+chB];
            float ba = sm[B2_BE2+chA], bb2 = sm[B2_BE2+chB];
#pragma unroll
            for (int ee=0; ee<2; ee++) {
                float a[2][4];
                upk2(acc[ee][0][0],a[0][0],a[0][1]); upk2(acc[ee][0][1],a[0][2],a[0][3]);
                upk2(acc[ee][1][0],a[1][0],a[1][1]); upk2(acc[ee][1][1],a[1][2],a[1][3]);
                float* outp = accum + (size_t)(ee?di1:di0)*256;
#pragma unroll
                for (int s = 0; s < 4; s++) {
                    float v0 = a[0][s] + xln[ee][0][s];
                    float v1 = a[1][s] + xln[ee][1][s];
                    lnpair(v0, v1, ga, gb, ba, bb2);
                    red2(outp + s*64 + lane*2, v0, v1);
                }
            }
            if (lane == 0) { atomicAdd(cnt+di0, 1.0f); atomicAdd(cnt+di1, 1.0f); }
        }
        __syncwarp();
    }
}

__global__ void __launch_bounds__(256) final_kernel(
    const float* __restrict__ Wout, const float* __restrict__ bout,
    float* __restrict__ out)
{
    __shared__ float WoT[2048];
    __shared__ float xs[8][64];
    const int tid = threadIdx.x;
    for (int i = tid; i < 2048; i += 256) {
        int o = i>>6, c = i&63;
        WoT[c*32+o] = Wout[i];
    }
    __syncthreads();
    const int wrp = tid>>5, lane = tid&31;
    const int n = blockIdx.x*8 + wrp;
    if (n >= NA_) return;
    float c0 = g_cnt[0][n], c1 = g_cnt[1][n];
    float i0 = (c0>0.f) ? 0.5f/c0 : 0.f;
    float i1 = (c1>0.f) ? 0.5f/c1 : 0.f;
    const float* a0p = &g_accum[0][n][0];
    const float* a1p = &g_accum[1][n][0];
    float s0 = 0.f, s1 = 0.f;
#pragma unroll
    for (int t = 0; t < 4; t++) {
        s0 += a0p[t*64+lane*2]  *i0 + a1p[t*64+lane*2]  *i1;
        s1 += a0p[t*64+lane*2+1]*i0 + a1p[t*64+lane*2+1]*i1;
    }
    xs[wrp][lane] = s0; xs[wrp][lane+32] = s1;
    __syncwarp();
    float lg = 4.0f*bout[lane];
#pragma unroll
    for (int c = 0; c < 64; c++) lg += xs[wrp][c]*WoT[c*32+lane];
    float m = lg;
#pragma unroll
    for (int o = 16; o; o >>= 1) m = fmaxf(m, __shfl_xor_sync(~0u, m, o));
    float ev = __expf(lg - m);
    float sum = ev;
#pragma unroll
    for (int o = 16; o; o >>= 1) sum += __shfl_xor_sync(~0u, sum, o);
    out[(size_t)n*32 + lane] = ev/sum;
}

extern "C" void kernel_launch(void* const* d_in, const int* in_sizes, int n_in,
                              void* d_out, int out_size) {
    const float* xA   = (const float*)d_in[0];
    const float* xB   = (const float*)d_in[1];
    const int*   e_ba = (const int*)d_in[2];
    const int*   e_aa = (const int*)d_in[3];
    const float* Wb   = (const float*)d_in[4];
    const float* bb   = (const float*)d_in[5];
    const float* Wqkv = (const float*)d_in[6];
    const float* bqkv = (const float*)d_in[7];
    const float* Wo   = (const float*)d_in[8];
    const float* bo   = (const float*)d_in[9];
    const float* g1   = (const float*)d_in[10];
    const float* be1  = (const float*)d_in[11];
    const float* W1   = (const float*)d_in[12];
    const float* bf1  = (const float*)d_in[13];
    const float* W2   = (const float*)d_in[14];
    const float* bf2  = (const float*)d_in[15];
    const float* g2   = (const float*)d_in[16];
    const float* be2  = (const float*)d_in[17];
    const float* Wout = (const float*)d_in[18];
    const float* bout = (const float*)d_in[19];

    cudaFuncSetAttribute(pre_dst_kernel,
                         cudaFuncAttributeMaxDynamicSharedMemorySize, PD_SMEM);
    cudaFuncSetAttribute(pre_src_kernel,
                         cudaFuncAttributeMaxDynamicSharedMemorySize, PS_SMEM);
    cudaFuncSetAttribute(edge_kernel,
                         cudaFuncAttributeMaxDynamicSharedMemorySize, SMEM_E);

    pre_dst_kernel<<<dim3(148,2), 256, PD_SMEM>>>(xA, Wqkv, bqkv);
    pre_src_kernel<<<dim3(148,2), 256, PS_SMEM>>>(xA, xB, Wb, bb, Wqkv, bqkv);
    edge_kernel<<<dim3(148,2), 32*NW, SMEM_E>>>(
        xA, e_ba, e_aa, Wo, bo, g1, be1, W1, bf1, W2, bf2, g2, be2);
    final_kernel<<<(NA_+7)/8, 256>>>(Wout, bout, (float*)d_out);
    zero_kernel<<<1024, 256>>>();
}